// round 3
// baseline (speedup 1.0000x reference)
#include <cuda_runtime.h>

#define B_    16
#define N_    400
#define P_    200
#define E_D   200
#define A_D   128
#define H_    8
#define PT    4      // pathways per block in kernel B

typedef unsigned long long u64;

// proj scratch, transposed pairs: g_projT[(b*64 + a2)*400 + n] = {proj[b,n,2a2], proj[b,n,2a2+1]}
__device__ u64 g_projT[B_ * 64 * N_];

__device__ __forceinline__ u64 pack2(float x, float y) {
    u64 r; asm("mov.b64 %0, {%1, %2};" : "=l"(r) : "f"(x), "f"(y)); return r;
}
__device__ __forceinline__ void unpack2(u64 v, float& x, float& y) {
    asm("mov.b64 {%0, %1}, %2;" : "=f"(x), "=f"(y) : "l"(v));
}
__device__ __forceinline__ u64 fma2(u64 a, u64 b, u64 c) {
    u64 d; asm("fma.rn.f32x2 %0, %1, %2, %3;" : "=l"(d) : "l"(a), "l"(b), "l"(c)); return d;
}
__device__ __forceinline__ u64 add2(u64 a, u64 b) {
    u64 d; asm("add.rn.f32x2 %0, %1, %2;" : "=l"(d) : "l"(a), "l"(b)); return d;
}
__device__ __forceinline__ float tanh_ap(float x) {
    float y; asm("tanh.approx.f32 %0, %1;" : "=f"(y) : "f"(x)); return y;
}
__device__ __forceinline__ u64 tanh2(u64 v) {
    float x, y; unpack2(v, x, y);
    return pack2(tanh_ap(x), tanh_ap(y));
}

// ---------------------------------------------------------------------------
// Kernel A: proj = emb_gene[omc] @ W0 + b0, written TRANSPOSED as float2 pairs.
// ---------------------------------------------------------------------------
__global__ __launch_bounds__(128) void kA(
    const int* __restrict__ omc, const float* __restrict__ eg,
    const float* __restrict__ W0, const float* __restrict__ b0)
{
    __shared__ float EsT[E_D * 8];   // [e][r]
    __shared__ int idxs[8];
    const int R0 = blockIdx.x * 8;
    const int b  = R0 / N_;
    const int nb = R0 - b * N_;
    const int t  = threadIdx.x;

    if (t < 8) idxs[t] = omc[R0 + t];
    __syncthreads();
    for (int i = t; i < 8 * E_D; i += 128) {
        int r = i / E_D, e = i - r * E_D;
        EsT[e * 8 + r] = eg[(long)idxs[r] * E_D + e];
    }
    __syncthreads();

    const int k  = t & 63;           // a-pair
    const int rg = t >> 6;           // row group (4 rows each)
    const u64* W2 = (const u64*)W0;  // [e][64] pairs
    const u64  bias = ((const u64*)b0)[k];

    u64 acc[4];
#pragma unroll
    for (int r = 0; r < 4; r++) acc[r] = bias;

#pragma unroll 4
    for (int e = 0; e < E_D; e++) {
        u64 w = W2[e * 64 + k];
        const float* er = EsT + e * 8 + rg * 4;
        acc[0] = fma2(pack2(er[0], er[0]), w, acc[0]);
        acc[1] = fma2(pack2(er[1], er[1]), w, acc[1]);
        acc[2] = fma2(pack2(er[2], er[2]), w, acc[2]);
        acc[3] = fma2(pack2(er[3], er[3]), w, acc[3]);
    }
#pragma unroll
    for (int r = 0; r < 4; r++)
        g_projT[(long)(b * 64 + k) * N_ + nb + rg * 4 + r] = acc[r];
}

// ---------------------------------------------------------------------------
// Kernel B (fused). Block = (b, tile of 4 pathways), 256 threads = 8 warps.
// Phase 1: warp w -> pathway PAIR (w&1): {0,1} or {2,3}; gene chunks
//          round-robin by j = w>>1. One proj load + one Wb read feed BOTH
//          pathways (16 FFMA2 per (a2, gene32) step) -> FMA-pipe bound.
// Phase 2/3: warp w -> pathway w>>1, half w&1 (heads / E-slice split).
//
// SMEM floats:
//   sc   [0, 12800)      scores PT*H*N      (reused as E-chunk 64x200 in ph3)
//   attn [12800, 14400)  PT*N
//   eps  [14400, 14912)  PT*A
//   wb2  [14912, 15936)  512 u64-pairs of Wb (16B aligned for LDS.128)
//   sinv [15936, 15968)  PT*H
//   bbs  [15968, 15976)
//   idxs [15976, 16040)  64 ints
// = 64160 bytes -> 3 blocks/SM
// ---------------------------------------------------------------------------
#define SMEM_B_BYTES (16040 * 4)

extern __shared__ float smemB[];

__global__ __launch_bounds__(256, 3) void kB(
    const int* __restrict__ omc, const int* __restrict__ ptw,
    const float* __restrict__ eg, const float* __restrict__ ept,
    const float* __restrict__ Wb, const float* __restrict__ bb,
    float* __restrict__ out)
{
    float* sc   = smemB;
    float* attn = smemB + 12800;
    float* eps  = smemB + 14400;
    float* wb2  = smemB + 14912;
    float* sinv = smemB + 15936;
    float* bbs  = smemB + 15968;
    int*   idxs = (int*)(smemB + 15976);

    const int bx   = blockIdx.x;
    const int b    = bx / 50;
    const int pt   = bx - b * 50;
    const int t    = threadIdx.x;
    const int w    = t >> 5;
    const int lane = t & 31;

    // ---- init loads -------------------------------------------------------
    for (int i = t; i < PT * A_D; i += 256) {
        int pl = i >> 7, a = i & 127;
        eps[i] = ept[(long)ptw[pt * PT + pl] * A_D + a];
    }
    for (int i = t; i < 512; i += 256) {          // (a2, h) pairs of Wb
        int a2 = i >> 3, h = i & 7;
        wb2[i * 2 + 0] = Wb[(2 * a2) * H_ + h];
        wb2[i * 2 + 1] = Wb[(2 * a2 + 1) * H_ + h];
    }
    if (t < 8) bbs[t] = bb[t];
    __syncthreads();

    const u64* wbp = (const u64*)wb2;

    // ---- Phase 1: scores, 2 pathways per warp -----------------------------
    {
        const int pair = w & 1;            // pathways pair*2, pair*2+1
        const int jw   = w >> 1;           // chunk round-robin 0..3
        const u64* epsA = (const u64*)(eps + (pair * 2 + 0) * A_D);
        const u64* epsB = (const u64*)(eps + (pair * 2 + 1) * A_D);
        float* scA = sc + (pair * 2 + 0) * H_ * N_;
        float* scB = sc + (pair * 2 + 1) * H_ * N_;
        float bh[H_];
#pragma unroll
        for (int h = 0; h < H_; h++) bh[h] = bbs[h];

        for (int k = jw; k * 32 < N_; k += 4) {
            const int gene = k * 32 + lane;
            const int gc   = min(gene, N_ - 1);
            const u64* pp = g_projT + (long)b * 25600 + gc;  // + a2*400

            u64 accA[H_], accB[H_];
#pragma unroll
            for (int h = 0; h < H_; h++) { accA[h] = 0ull; accB[h] = 0ull; }

#pragma unroll
            for (int a0 = 0; a0 < 64; a0 += 8) {
                u64 pr[8];
#pragma unroll
                for (int j = 0; j < 8; j++) pr[j] = pp[(a0 + j) * N_];
#pragma unroll
                for (int j = 0; j < 8; j++) {
                    const int a2 = a0 + j;
                    u64 tA = tanh2(add2(pr[j], epsA[a2]));
                    u64 tB = tanh2(add2(pr[j], epsB[a2]));
                    const ulonglong2* w2 = (const ulonglong2*)(wbp + a2 * 8);
                    ulonglong2 w01 = w2[0], w23 = w2[1], w45 = w2[2], w67 = w2[3];
                    accA[0] = fma2(tA, w01.x, accA[0]);
                    accB[0] = fma2(tB, w01.x, accB[0]);
                    accA[1] = fma2(tA, w01.y, accA[1]);
                    accB[1] = fma2(tB, w01.y, accB[1]);
                    accA[2] = fma2(tA, w23.x, accA[2]);
                    accB[2] = fma2(tB, w23.x, accB[2]);
                    accA[3] = fma2(tA, w23.y, accA[3]);
                    accB[3] = fma2(tB, w23.y, accB[3]);
                    accA[4] = fma2(tA, w45.x, accA[4]);
                    accB[4] = fma2(tB, w45.x, accB[4]);
                    accA[5] = fma2(tA, w45.y, accA[5]);
                    accB[5] = fma2(tB, w45.y, accB[5]);
                    accA[6] = fma2(tA, w67.x, accA[6]);
                    accB[6] = fma2(tB, w67.x, accB[6]);
                    accA[7] = fma2(tA, w67.y, accA[7]);
                    accB[7] = fma2(tB, w67.y, accB[7]);
                }
            }
            if (gene < N_) {
#pragma unroll
                for (int h = 0; h < H_; h++) {
                    float x, y;
                    unpack2(accA[h], x, y);
                    scA[h * N_ + gene] = x + y + bh[h];
                    unpack2(accB[h], x, y);
                    scB[h * N_ + gene] = x + y + bh[h];
                }
            }
        }
    }
    __syncthreads();

    // ---- Phase 2: softmax over n per head; attn = sum_h -------------------
    const int p    = w >> 1;
    const int half = w & 1;
    const int pg   = pt * PT + p;
    float* scp = sc + p * H_ * N_;
#pragma unroll
    for (int q = 0; q < 4; q++) {
        const int h = half * 4 + q;
        float* row = scp + h * N_;
        float m = -1e30f;
        for (int i = lane; i < N_; i += 32) m = fmaxf(m, row[i]);
#pragma unroll
        for (int o = 16; o; o >>= 1) m = fmaxf(m, __shfl_xor_sync(0xffffffffu, m, o));
        float s = 0.f;
        for (int i = lane; i < N_; i += 32) {
            float e = __expf(row[i] - m);
            row[i] = e;
            s += e;
        }
#pragma unroll
        for (int o = 16; o; o >>= 1) s += __shfl_xor_sync(0xffffffffu, s, o);
        if (lane == 0) sinv[p * H_ + h] = __fdividef(1.f, s);
    }
    __syncthreads();

    {
        float iv[H_];
#pragma unroll
        for (int h = 0; h < H_; h++) iv[h] = sinv[p * H_ + h];
        for (int i = lane; i < 200; i += 32) {
            const int n = half * 200 + i;
            float a = 0.f;
#pragma unroll
            for (int h = 0; h < H_; h++) a = fmaf(scp[h * N_ + n], iv[h], a);
            attn[p * N_ + n] = a;
        }
    }

    // ---- Phase 3: out[b,pg,:] = sum_n attn[n] * E[b,n,:] ------------------
    const u64* eg2 = (const u64*)eg;        // 100 u64 per vocab row
    u64* Es = (u64*)sc;                     // 64 genes x 100 u64 (fits exactly)
    const float* ap = attn + p * N_;
    const int j0 = half * 50;               // this warp's E-slice (u64 units)
    u64 acc0 = 0ull, acc1 = 0ull;

    for (int c = 0; c < 7; c++) {
        const int n0 = c * 64;
        const int cnt = min(64, N_ - n0);
        __syncthreads();                    // protect Es/idxs reuse
        if (t < cnt) idxs[t] = omc[b * N_ + n0 + t];
        __syncthreads();
        for (int i = t; i < cnt * 100; i += 256) {
            int n = i / 100, e2 = i - n * 100;
            Es[n * 100 + e2] = eg2[(long)idxs[n] * 100 + e2];
        }
        __syncthreads();

#pragma unroll 2
        for (int n = 0; n < cnt; n++) {
            float a = ap[n0 + n];
            u64 av = pack2(a, a);
            const u64* er = Es + n * 100;
            acc0 = fma2(er[j0 + lane], av, acc0);
            if (lane < 18) acc1 = fma2(er[j0 + 32 + lane], av, acc1);
        }
    }

    u64* op = (u64*)out + (long)(b * P_ + pg) * 100;
    op[j0 + lane] = acc0;
    if (lane < 18) op[j0 + 32 + lane] = acc1;
}

// ---------------------------------------------------------------------------
extern "C" void kernel_launch(void* const* d_in, const int* in_sizes, int n_in,
                              void* d_out, int out_size)
{
    const int*   omc = (const int*)  d_in[0];
    const int*   ptw = (const int*)  d_in[1];
    const float* eg  = (const float*)d_in[2];
    const float* ept = (const float*)d_in[3];
    const float* W0  = (const float*)d_in[4];
    const float* b0  = (const float*)d_in[5];
    const float* Wb  = (const float*)d_in[6];
    const float* bb  = (const float*)d_in[7];
    float* out = (float*)d_out;

    kA<<<(B_ * N_) / 8, 128>>>(omc, eg, W0, b0);

    cudaFuncSetAttribute(kB, cudaFuncAttributeMaxDynamicSharedMemorySize,
                         SMEM_B_BYTES);
    kB<<<B_ * (P_ / PT), 256, SMEM_B_BYTES>>>(omc, ptw, eg, ept, Wb, bb, out);
}

// round 4
// speedup vs baseline: 1.1341x; 1.1341x over previous
#include <cuda_runtime.h>

#define B_    16
#define N_    400
#define P_    200
#define E_D   200
#define A_D   128
#define H_    8
#define PT    4      // pathways per block in kernel B

typedef unsigned long long u64;

// proj scratch, transposed pairs: g_projT[(b*64 + a2)*400 + n] = {proj[b,n,2a2], proj[b,n,2a2+1]}
__device__ u64 g_projT[B_ * 64 * N_];

__device__ __forceinline__ u64 pack2(float x, float y) {
    u64 r; asm("mov.b64 %0, {%1, %2};" : "=l"(r) : "f"(x), "f"(y)); return r;
}
__device__ __forceinline__ void unpack2(u64 v, float& x, float& y) {
    asm("mov.b64 {%0, %1}, %2;" : "=f"(x), "=f"(y) : "l"(v));
}
__device__ __forceinline__ u64 fma2(u64 a, u64 b, u64 c) {
    u64 d; asm("fma.rn.f32x2 %0, %1, %2, %3;" : "=l"(d) : "l"(a), "l"(b), "l"(c)); return d;
}
__device__ __forceinline__ u64 add2(u64 a, u64 b) {
    u64 d; asm("add.rn.f32x2 %0, %1, %2;" : "=l"(d) : "l"(a), "l"(b)); return d;
}
__device__ __forceinline__ float tanh_ap(float x) {
    float y; asm("tanh.approx.f32 %0, %1;" : "=f"(y) : "f"(x)); return y;
}
__device__ __forceinline__ u64 tanh2(u64 v) {
    float x, y; unpack2(v, x, y);
    return pack2(tanh_ap(x), tanh_ap(y));
}

// ---------------------------------------------------------------------------
// Kernel A: proj = emb_gene[omc] @ W0 + b0, written TRANSPOSED as float2 pairs.
// ---------------------------------------------------------------------------
__global__ __launch_bounds__(128) void kA(
    const int* __restrict__ omc, const float* __restrict__ eg,
    const float* __restrict__ W0, const float* __restrict__ b0)
{
    __shared__ float EsT[E_D * 8];   // [e][r]
    __shared__ int idxs[8];
    const int R0 = blockIdx.x * 8;
    const int b  = R0 / N_;
    const int nb = R0 - b * N_;
    const int t  = threadIdx.x;

    if (t < 8) idxs[t] = omc[R0 + t];
    __syncthreads();
    for (int i = t; i < 8 * E_D; i += 128) {
        int r = i / E_D, e = i - r * E_D;
        EsT[e * 8 + r] = eg[(long)idxs[r] * E_D + e];
    }
    __syncthreads();

    const int k  = t & 63;           // a-pair
    const int rg = t >> 6;           // row group (4 rows each)
    const u64* W2 = (const u64*)W0;  // [e][64] pairs
    const u64  bias = ((const u64*)b0)[k];

    u64 acc[4];
#pragma unroll
    for (int r = 0; r < 4; r++) acc[r] = bias;

#pragma unroll 4
    for (int e = 0; e < E_D; e++) {
        u64 w = W2[e * 64 + k];
        const float* er = EsT + e * 8 + rg * 4;
        acc[0] = fma2(pack2(er[0], er[0]), w, acc[0]);
        acc[1] = fma2(pack2(er[1], er[1]), w, acc[1]);
        acc[2] = fma2(pack2(er[2], er[2]), w, acc[2]);
        acc[3] = fma2(pack2(er[3], er[3]), w, acc[3]);
    }
#pragma unroll
    for (int r = 0; r < 4; r++)
        g_projT[(long)(b * 64 + k) * N_ + nb + rg * 4 + r] = acc[r];
}

// ---------------------------------------------------------------------------
// Kernel B (fused). Block = (b, tile of 4 pathways), 256 threads = 8 warps.
// Phase 1: warp w -> pathway PAIR (w&1); gene chunks round-robin by w>>1.
//          One proj load + one Wb read feed BOTH pathways (16 FFMA2 per
//          (a2, gene32) step) -> FMA-pipe bound.
//          NOTE: needs ~110 live regs (32 u64 accs) -> launch_bounds(256,2).
// Phase 2/3: warp w -> pathway w>>1, half w&1 (heads / E-slice split).
//
// SMEM floats:
//   sc   [0, 12800)      scores PT*H*N      (reused as E-chunk 64x200 in ph3)
//   attn [12800, 14400)  PT*N
//   eps  [14400, 14912)  PT*A
//   wb2  [14912, 15936)  512 u64-pairs of Wb (16B aligned for LDS.128)
//   sinv [15936, 15968)  PT*H
//   bbs  [15968, 15976)
//   idxs [15976, 16040)  64 ints
// = 64160 bytes
// ---------------------------------------------------------------------------
#define SMEM_B_BYTES (16040 * 4)

extern __shared__ float smemB[];

__global__ __launch_bounds__(256, 2) void kB(
    const int* __restrict__ omc, const int* __restrict__ ptw,
    const float* __restrict__ eg, const float* __restrict__ ept,
    const float* __restrict__ Wb, const float* __restrict__ bb,
    float* __restrict__ out)
{
    float* sc   = smemB;
    float* attn = smemB + 12800;
    float* eps  = smemB + 14400;
    float* wb2  = smemB + 14912;
    float* sinv = smemB + 15936;
    float* bbs  = smemB + 15968;
    int*   idxs = (int*)(smemB + 15976);

    const int bx   = blockIdx.x;
    const int b    = bx / 50;
    const int pt   = bx - b * 50;
    const int t    = threadIdx.x;
    const int w    = t >> 5;
    const int lane = t & 31;

    // ---- init loads -------------------------------------------------------
    for (int i = t; i < PT * A_D; i += 256) {
        int pl = i >> 7, a = i & 127;
        eps[i] = ept[(long)ptw[pt * PT + pl] * A_D + a];
    }
    for (int i = t; i < 512; i += 256) {          // (a2, h) pairs of Wb
        int a2 = i >> 3, h = i & 7;
        wb2[i * 2 + 0] = Wb[(2 * a2) * H_ + h];
        wb2[i * 2 + 1] = Wb[(2 * a2 + 1) * H_ + h];
    }
    if (t < 8) bbs[t] = bb[t];
    __syncthreads();

    const u64* wbp = (const u64*)wb2;

    // ---- Phase 1: scores, 2 pathways per warp -----------------------------
    {
        const int pair = w & 1;            // pathways pair*2, pair*2+1
        const int jw   = w >> 1;           // chunk round-robin 0..3
        const u64* epsA = (const u64*)(eps + (pair * 2 + 0) * A_D);
        const u64* epsB = (const u64*)(eps + (pair * 2 + 1) * A_D);
        float* scA = sc + (pair * 2 + 0) * H_ * N_;
        float* scB = sc + (pair * 2 + 1) * H_ * N_;

        for (int k = jw; k * 32 < N_; k += 4) {
            const int gene = k * 32 + lane;
            const int gc   = min(gene, N_ - 1);
            const u64* pp = g_projT + (long)b * 25600 + gc;  // + a2*400

            u64 accA[H_], accB[H_];
#pragma unroll
            for (int h = 0; h < H_; h++) { accA[h] = 0ull; accB[h] = 0ull; }

#pragma unroll
            for (int a0 = 0; a0 < 64; a0 += 8) {
                u64 pr[8];
#pragma unroll
                for (int j = 0; j < 8; j++) pr[j] = pp[(a0 + j) * N_];
#pragma unroll
                for (int j = 0; j < 8; j++) {
                    const int a2 = a0 + j;
                    u64 tA = tanh2(add2(pr[j], epsA[a2]));
                    u64 tB = tanh2(add2(pr[j], epsB[a2]));
                    const ulonglong2* w2 = (const ulonglong2*)(wbp + a2 * 8);
                    ulonglong2 w01 = w2[0];
                    accA[0] = fma2(tA, w01.x, accA[0]);
                    accB[0] = fma2(tB, w01.x, accB[0]);
                    accA[1] = fma2(tA, w01.y, accA[1]);
                    accB[1] = fma2(tB, w01.y, accB[1]);
                    ulonglong2 w23 = w2[1];
                    accA[2] = fma2(tA, w23.x, accA[2]);
                    accB[2] = fma2(tB, w23.x, accB[2]);
                    accA[3] = fma2(tA, w23.y, accA[3]);
                    accB[3] = fma2(tB, w23.y, accB[3]);
                    ulonglong2 w45 = w2[2];
                    accA[4] = fma2(tA, w45.x, accA[4]);
                    accB[4] = fma2(tB, w45.x, accB[4]);
                    accA[5] = fma2(tA, w45.y, accA[5]);
                    accB[5] = fma2(tB, w45.y, accB[5]);
                    ulonglong2 w67 = w2[3];
                    accA[6] = fma2(tA, w67.x, accA[6]);
                    accB[6] = fma2(tB, w67.x, accB[6]);
                    accA[7] = fma2(tA, w67.y, accA[7]);
                    accB[7] = fma2(tB, w67.y, accB[7]);
                }
            }
            if (gene < N_) {
#pragma unroll
                for (int h = 0; h < H_; h++) {
                    float x, y;
                    unpack2(accA[h], x, y);
                    scA[h * N_ + gene] = x + y + bbs[h];
                    unpack2(accB[h], x, y);
                    scB[h * N_ + gene] = x + y + bbs[h];
                }
            }
        }
    }
    __syncthreads();

    // ---- Phase 2: softmax over n per head; attn = sum_h -------------------
    const int p    = w >> 1;
    const int half = w & 1;
    const int pg   = pt * PT + p;
    float* scp = sc + p * H_ * N_;
#pragma unroll
    for (int q = 0; q < 4; q++) {
        const int h = half * 4 + q;
        float* row = scp + h * N_;
        float m = -1e30f;
        for (int i = lane; i < N_; i += 32) m = fmaxf(m, row[i]);
#pragma unroll
        for (int o = 16; o; o >>= 1) m = fmaxf(m, __shfl_xor_sync(0xffffffffu, m, o));
        float s = 0.f;
        for (int i = lane; i < N_; i += 32) {
            float e = __expf(row[i] - m);
            row[i] = e;
            s += e;
        }
#pragma unroll
        for (int o = 16; o; o >>= 1) s += __shfl_xor_sync(0xffffffffu, s, o);
        if (lane == 0) sinv[p * H_ + h] = __fdividef(1.f, s);
    }
    __syncthreads();

    {
        float iv[H_];
#pragma unroll
        for (int h = 0; h < H_; h++) iv[h] = sinv[p * H_ + h];
        for (int i = lane; i < 200; i += 32) {
            const int n = half * 200 + i;
            float a = 0.f;
#pragma unroll
            for (int h = 0; h < H_; h++) a = fmaf(scp[h * N_ + n], iv[h], a);
            attn[p * N_ + n] = a;
        }
    }

    // ---- Phase 3: out[b,pg,:] = sum_n attn[n] * E[b,n,:] ------------------
    const u64* eg2 = (const u64*)eg;        // 100 u64 per vocab row
    u64* Es = (u64*)sc;                     // 64 genes x 100 u64 (fits exactly)
    const float* ap = attn + p * N_;
    const int j0 = half * 50;               // this warp's E-slice (u64 units)
    u64 acc0 = 0ull, acc1 = 0ull;

    for (int c = 0; c < 7; c++) {
        const int n0 = c * 64;
        const int cnt = min(64, N_ - n0);
        __syncthreads();                    // protect Es/idxs reuse
        if (t < cnt) idxs[t] = omc[b * N_ + n0 + t];
        __syncthreads();
        for (int i = t; i < cnt * 100; i += 256) {
            int n = i / 100, e2 = i - n * 100;
            Es[n * 100 + e2] = eg2[(long)idxs[n] * 100 + e2];
        }
        __syncthreads();

#pragma unroll 2
        for (int n = 0; n < cnt; n++) {
            float a = ap[n0 + n];
            u64 av = pack2(a, a);
            const u64* er = Es + n * 100;
            acc0 = fma2(er[j0 + lane], av, acc0);
            if (lane < 18) acc1 = fma2(er[j0 + 32 + lane], av, acc1);
        }
    }

    u64* op = (u64*)out + (long)(b * P_ + pg) * 100;
    op[j0 + lane] = acc0;
    if (lane < 18) op[j0 + 32 + lane] = acc1;
}

// ---------------------------------------------------------------------------
extern "C" void kernel_launch(void* const* d_in, const int* in_sizes, int n_in,
                              void* d_out, int out_size)
{
    const int*   omc = (const int*)  d_in[0];
    const int*   ptw = (const int*)  d_in[1];
    const float* eg  = (const float*)d_in[2];
    const float* ept = (const float*)d_in[3];
    const float* W0  = (const float*)d_in[4];
    const float* b0  = (const float*)d_in[5];
    const float* Wb  = (const float*)d_in[6];
    const float* bb  = (const float*)d_in[7];
    float* out = (float*)d_out;

    kA<<<(B_ * N_) / 8, 128>>>(omc, eg, W0, b0);

    cudaFuncSetAttribute(kB, cudaFuncAttributeMaxDynamicSharedMemorySize,
                         SMEM_B_BYTES);
    kB<<<B_ * (P_ / PT), 256, SMEM_B_BYTES>>>(omc, ptw, eg, ept, Wb, bb, out);
}

// round 5
// speedup vs baseline: 5.2716x; 4.6484x over previous
#include <cuda_runtime.h>

#define B_    16
#define N_    400
#define P_    200
#define E_D   200
#define A_D   128
#define H_    8
#define PT    4      // pathways per block in kernel B

typedef unsigned long long u64;

// proj scratch, transposed pairs: g_projT[(b*64 + a2)*400 + n] = {proj[b,n,2a2], proj[b,n,2a2+1]}
__device__ u64 g_projT[B_ * 64 * N_];

__device__ __forceinline__ u64 pack2(float x, float y) {
    u64 r; asm("mov.b64 %0, {%1, %2};" : "=l"(r) : "f"(x), "f"(y)); return r;
}
__device__ __forceinline__ void unpack2(u64 v, float& x, float& y) {
    asm("mov.b64 {%0, %1}, %2;" : "=f"(x), "=f"(y) : "l"(v));
}
__device__ __forceinline__ u64 fma2(u64 a, u64 b, u64 c) {
    u64 d; asm("fma.rn.f32x2 %0, %1, %2, %3;" : "=l"(d) : "l"(a), "l"(b), "l"(c)); return d;
}
__device__ __forceinline__ u64 add2(u64 a, u64 b) {
    u64 d; asm("add.rn.f32x2 %0, %1, %2;" : "=l"(d) : "l"(a), "l"(b)); return d;
}
__device__ __forceinline__ float tanh_ap(float x) {
    float y; asm("tanh.approx.f32 %0, %1;" : "=f"(y) : "f"(x)); return y;
}
__device__ __forceinline__ u64 tanh2(u64 v) {
    float x, y; unpack2(v, x, y);
    return pack2(tanh_ap(x), tanh_ap(y));
}

// ---------------------------------------------------------------------------
// Kernel A: proj = emb_gene[omc] @ W0 + b0, written TRANSPOSED as float2 pairs.
// ---------------------------------------------------------------------------
__global__ __launch_bounds__(128) void kA(
    const int* __restrict__ omc, const float* __restrict__ eg,
    const float* __restrict__ W0, const float* __restrict__ b0)
{
    __shared__ float EsT[E_D * 8];   // [e][r]
    __shared__ int idxs[8];
    const int R0 = blockIdx.x * 8;
    const int b  = R0 / N_;
    const int nb = R0 - b * N_;
    const int t  = threadIdx.x;

    if (t < 8) idxs[t] = omc[R0 + t];
    __syncthreads();
    for (int i = t; i < 8 * E_D; i += 128) {
        int r = i / E_D, e = i - r * E_D;
        EsT[e * 8 + r] = eg[(long)idxs[r] * E_D + e];
    }
    __syncthreads();

    const int k  = t & 63;           // a-pair
    const int rg = t >> 6;           // row group (4 rows each)
    const u64* W2 = (const u64*)W0;  // [e][64] pairs
    const u64  bias = ((const u64*)b0)[k];

    u64 acc[4];
#pragma unroll
    for (int r = 0; r < 4; r++) acc[r] = bias;

#pragma unroll 4
    for (int e = 0; e < E_D; e++) {
        u64 w = W2[e * 64 + k];
        const float* er = EsT + e * 8 + rg * 4;
        acc[0] = fma2(pack2(er[0], er[0]), w, acc[0]);
        acc[1] = fma2(pack2(er[1], er[1]), w, acc[1]);
        acc[2] = fma2(pack2(er[2], er[2]), w, acc[2]);
        acc[3] = fma2(pack2(er[3], er[3]), w, acc[3]);
    }
#pragma unroll
    for (int r = 0; r < 4; r++)
        g_projT[(long)(b * 64 + k) * N_ + nb + rg * 4 + r] = acc[r];
}

// ---------------------------------------------------------------------------
// Kernel B (fused). Block = (b, tile of 4 pathways), 256 threads = 8 warps.
// Phase 1: warp w -> pathway PAIR (w&1); gene chunks round-robin by w>>1.
//          One proj LDG + one Wb LDS.128-quad feed BOTH pathways.
//          Batch loop is unroll-1 with manual pr/nxt double buffer: MLP=8,
//          no ptxas hoist-spill (R3/R4 failure mode).
// Phase 2/3: warp w -> pathway w>>1, half w&1 (heads / E-slice split).
//
// SMEM floats:
//   sc    [0, 12800)      scores PT*H*N      (reused as E-chunk 64x200 in ph3)
//   attn  [12800, 14400)  PT*N
//   epsAB [14400, 14912)  2 pairs x 64 x float4 {pA_lo,pA_hi,pB_lo,pB_hi}
//   wb2   [14912, 15936)  512 u64-pairs of Wb (16B aligned for LDS.128)
//   sinv  [15936, 15968)  PT*H
//   bbs   [15968, 15976)
//   idxs  [15976, 16040)  64 ints
// = 64160 bytes
// ---------------------------------------------------------------------------
#define SMEM_B_BYTES (16040 * 4)

extern __shared__ float smemB[];

__global__ __launch_bounds__(256, 2) void kB(
    const int* __restrict__ omc, const int* __restrict__ ptw,
    const float* __restrict__ eg, const float* __restrict__ ept,
    const float* __restrict__ Wb, const float* __restrict__ bb,
    float* __restrict__ out)
{
    float* sc    = smemB;
    float* attn  = smemB + 12800;
    float* epsAB = smemB + 14400;
    float* wb2   = smemB + 14912;
    float* sinv  = smemB + 15936;
    float* bbs   = smemB + 15968;
    int*   idxs  = (int*)(smemB + 15976);

    const int bx   = blockIdx.x;
    const int b    = bx / 50;
    const int pt   = bx - b * 50;
    const int t    = threadIdx.x;
    const int w    = t >> 5;
    const int lane = t & 31;

    // ---- init loads -------------------------------------------------------
    // epsAB[pair][a2] = {ep[2p][2a2], ep[2p][2a2+1], ep[2p+1][2a2], ep[2p+1][2a2+1]}
    for (int i = t; i < 512; i += 256) {
        int pairI = i >> 8;            // 0..1
        int rem   = i & 255;
        int a2    = rem >> 2;
        int c     = rem & 3;           // 0,1 -> pathway 2*pair; 2,3 -> +1
        int pl    = pairI * 2 + (c >> 1);
        epsAB[i] = ept[(long)ptw[pt * PT + pl] * A_D + 2 * a2 + (c & 1)];
    }
    for (int i = t; i < 512; i += 256) {          // (a2, h) pairs of Wb
        int a2 = i >> 3, h = i & 7;
        wb2[i * 2 + 0] = Wb[(2 * a2) * H_ + h];
        wb2[i * 2 + 1] = Wb[(2 * a2 + 1) * H_ + h];
    }
    if (t < 8) bbs[t] = bb[t];
    __syncthreads();

    const u64* wbp = (const u64*)wb2;

    // ---- Phase 1: scores, 2 pathways per warp -----------------------------
    {
        const int pair = w & 1;            // pathways pair*2, pair*2+1
        const int jw   = w >> 1;           // chunk round-robin 0..3
        const ulonglong2* epsp = (const ulonglong2*)(epsAB + pair * 256);
        float* scA = sc + (pair * 2 + 0) * H_ * N_;
        float* scB = sc + (pair * 2 + 1) * H_ * N_;

        for (int k = jw; k * 32 < N_; k += 4) {
            const int gene = k * 32 + lane;
            const int gc   = min(gene, N_ - 1);
            const u64* pp = g_projT + (long)b * 25600 + gc;  // + a2*400

            u64 accA[H_], accB[H_];
#pragma unroll
            for (int h = 0; h < H_; h++) { accA[h] = 0ull; accB[h] = 0ull; }

            u64 pr[8], nxt[8];
#pragma unroll
            for (int j = 0; j < 8; j++) pr[j] = pp[j * N_];

#pragma unroll 1
            for (int a0 = 0; a0 < 64; a0 += 8) {
                if (a0 < 56) {
#pragma unroll
                    for (int j = 0; j < 8; j++) nxt[j] = pp[(a0 + 8 + j) * N_];
                }
#pragma unroll
                for (int j = 0; j < 8; j++) {
                    const int a2 = a0 + j;
                    ulonglong2 e2 = epsp[a2];
                    u64 tA = tanh2(add2(pr[j], e2.x));
                    u64 tB = tanh2(add2(pr[j], e2.y));
                    const ulonglong2* w2 = (const ulonglong2*)(wbp + a2 * 8);
                    ulonglong2 w01 = w2[0];
                    accA[0] = fma2(tA, w01.x, accA[0]);
                    accB[0] = fma2(tB, w01.x, accB[0]);
                    accA[1] = fma2(tA, w01.y, accA[1]);
                    accB[1] = fma2(tB, w01.y, accB[1]);
                    ulonglong2 w23 = w2[1];
                    accA[2] = fma2(tA, w23.x, accA[2]);
                    accB[2] = fma2(tB, w23.x, accB[2]);
                    accA[3] = fma2(tA, w23.y, accA[3]);
                    accB[3] = fma2(tB, w23.y, accB[3]);
                    ulonglong2 w45 = w2[2];
                    accA[4] = fma2(tA, w45.x, accA[4]);
                    accB[4] = fma2(tB, w45.x, accB[4]);
                    accA[5] = fma2(tA, w45.y, accA[5]);
                    accB[5] = fma2(tB, w45.y, accB[5]);
                    ulonglong2 w67 = w2[3];
                    accA[6] = fma2(tA, w67.x, accA[6]);
                    accB[6] = fma2(tB, w67.x, accB[6]);
                    accA[7] = fma2(tA, w67.y, accA[7]);
                    accB[7] = fma2(tB, w67.y, accB[7]);
                }
#pragma unroll
                for (int j = 0; j < 8; j++) pr[j] = nxt[j];
            }
            if (gene < N_) {
#pragma unroll
                for (int h = 0; h < H_; h++) {
                    float x, y;
                    unpack2(accA[h], x, y);
                    scA[h * N_ + gene] = x + y + bbs[h];
                    unpack2(accB[h], x, y);
                    scB[h * N_ + gene] = x + y + bbs[h];
                }
            }
        }
    }
    __syncthreads();

    // ---- Phase 2: softmax over n per head; attn = sum_h -------------------
    const int p    = w >> 1;
    const int half = w & 1;
    const int pg   = pt * PT + p;
    float* scp = sc + p * H_ * N_;
#pragma unroll
    for (int q = 0; q < 4; q++) {
        const int h = half * 4 + q;
        float* row = scp + h * N_;
        float m = -1e30f;
        for (int i = lane; i < N_; i += 32) m = fmaxf(m, row[i]);
#pragma unroll
        for (int o = 16; o; o >>= 1) m = fmaxf(m, __shfl_xor_sync(0xffffffffu, m, o));
        float s = 0.f;
        for (int i = lane; i < N_; i += 32) {
            float e = __expf(row[i] - m);
            row[i] = e;
            s += e;
        }
#pragma unroll
        for (int o = 16; o; o >>= 1) s += __shfl_xor_sync(0xffffffffu, s, o);
        if (lane == 0) sinv[p * H_ + h] = __fdividef(1.f, s);
    }
    __syncthreads();

    {
        float iv[H_];
#pragma unroll
        for (int h = 0; h < H_; h++) iv[h] = sinv[p * H_ + h];
        for (int i = lane; i < 200; i += 32) {
            const int n = half * 200 + i;
            float a = 0.f;
#pragma unroll
            for (int h = 0; h < H_; h++) a = fmaf(scp[h * N_ + n], iv[h], a);
            attn[p * N_ + n] = a;
        }
    }

    // ---- Phase 3: out[b,pg,:] = sum_n attn[n] * E[b,n,:] ------------------
    const u64* eg2 = (const u64*)eg;        // 100 u64 per vocab row
    u64* Es = (u64*)sc;                     // 64 genes x 100 u64 (fits exactly)
    const float* ap = attn + p * N_;
    const int j0 = half * 50;               // this warp's E-slice (u64 units)
    u64 acc0 = 0ull, acc1 = 0ull;

    for (int c = 0; c < 7; c++) {
        const int n0 = c * 64;
        const int cnt = min(64, N_ - n0);
        __syncthreads();                    // protect Es/idxs reuse
        if (t < cnt) idxs[t] = omc[b * N_ + n0 + t];
        __syncthreads();
        for (int i = t; i < cnt * 100; i += 256) {
            int n = i / 100, e2 = i - n * 100;
            Es[n * 100 + e2] = eg2[(long)idxs[n] * 100 + e2];
        }
        __syncthreads();

#pragma unroll 2
        for (int n = 0; n < cnt; n++) {
            float a = ap[n0 + n];
            u64 av = pack2(a, a);
            const u64* er = Es + n * 100;
            acc0 = fma2(er[j0 + lane], av, acc0);
            if (lane < 18) acc1 = fma2(er[j0 + 32 + lane], av, acc1);
        }
    }

    u64* op = (u64*)out + (long)(b * P_ + pg) * 100;
    op[j0 + lane] = acc0;
    if (lane < 18) op[j0 + 32 + lane] = acc1;
}

// ---------------------------------------------------------------------------
extern "C" void kernel_launch(void* const* d_in, const int* in_sizes, int n_in,
                              void* d_out, int out_size)
{
    const int*   omc = (const int*)  d_in[0];
    const int*   ptw = (const int*)  d_in[1];
    const float* eg  = (const float*)d_in[2];
    const float* ept = (const float*)d_in[3];
    const float* W0  = (const float*)d_in[4];
    const float* b0  = (const float*)d_in[5];
    const float* Wb  = (const float*)d_in[6];
    const float* bb  = (const float*)d_in[7];
    float* out = (float*)d_out;

    kA<<<(B_ * N_) / 8, 128>>>(omc, eg, W0, b0);

    cudaFuncSetAttribute(kB, cudaFuncAttributeMaxDynamicSharedMemorySize,
                         SMEM_B_BYTES);
    kB<<<B_ * (P_ / PT), 256, SMEM_B_BYTES>>>(omc, ptw, eg, ept, Wb, bb, out);
}

// round 6
// speedup vs baseline: 5.7270x; 1.0864x over previous
#include <cuda_runtime.h>

#define B_    16
#define N_    400
#define P_    200
#define E_D   200
#define A_D   128
#define H_    8
#define PT    4      // pathways per block in kernel B
#define NCH   7      // gene chunks of 64 (6 full + 1 partial of 16)

typedef unsigned long long u64;

// proj scratch, gene-paired: u64 at ((b*7 + chunk)*128 + a)*32 + lane =
//   { proj[gene=chunk*64+lane][a], proj[gene=chunk*64+32+lane][a] }   (chunk<6)
//   chunk 6 (genes 384..399): lane<8: { proj[384+lane][a], proj[392+lane][a] }
__device__ u64 g_projP[B_ * NCH * A_D * 32];

__device__ __forceinline__ u64 pack2(float x, float y) {
    u64 r; asm("mov.b64 %0, {%1, %2};" : "=l"(r) : "f"(x), "f"(y)); return r;
}
__device__ __forceinline__ void unpack2(u64 v, float& x, float& y) {
    asm("mov.b64 {%0, %1}, %2;" : "=f"(x), "=f"(y) : "l"(v));
}
__device__ __forceinline__ u64 fma2(u64 a, u64 b, u64 c) {
    u64 d; asm("fma.rn.f32x2 %0, %1, %2, %3;" : "=l"(d) : "l"(a), "l"(b), "l"(c)); return d;
}
__device__ __forceinline__ u64 add2(u64 a, u64 b) {
    u64 d; asm("add.rn.f32x2 %0, %1, %2;" : "=l"(d) : "l"(a), "l"(b)); return d;
}
__device__ __forceinline__ float tanh_ap(float x) {
    float y; asm("tanh.approx.f32 %0, %1;" : "=f"(y) : "f"(x)); return y;
}
__device__ __forceinline__ u64 tanh2(u64 v) {
    float x, y; unpack2(v, x, y);
    return pack2(tanh_ap(x), tanh_ap(y));
}

// ---------------------------------------------------------------------------
// Kernel A: proj = emb_gene[omc] @ W0 + b0, scattered into gene-paired layout.
// Block = 8 rows (one b). t = (rg, k): k = a-pair 0..63, rg = row-group 0..1.
// ---------------------------------------------------------------------------
__global__ __launch_bounds__(128) void kA(
    const int* __restrict__ omc, const float* __restrict__ eg,
    const float* __restrict__ W0, const float* __restrict__ b0)
{
    __shared__ float EsT[E_D * 8];   // [e][r]
    __shared__ int idxs[8];
    const int R0 = blockIdx.x * 8;
    const int b  = R0 / N_;
    const int nb = R0 - b * N_;
    const int t  = threadIdx.x;

    if (t < 8) idxs[t] = omc[R0 + t];
    __syncthreads();
    for (int i = t; i < 8 * E_D; i += 128) {
        int r = i / E_D, e = i - r * E_D;
        EsT[e * 8 + r] = eg[(long)idxs[r] * E_D + e];
    }
    __syncthreads();

    const int k  = t & 63;           // a-pair: a = 2k, 2k+1
    const int rg = t >> 6;           // row group (4 rows each)
    const u64* W2 = (const u64*)W0;  // [e][64] pairs
    const u64  bias = ((const u64*)b0)[k];

    u64 acc[4];
#pragma unroll
    for (int r = 0; r < 4; r++) acc[r] = bias;

#pragma unroll 4
    for (int e = 0; e < E_D; e++) {
        u64 w = W2[e * 64 + k];
        const float* er = EsT + e * 8 + rg * 4;
        acc[0] = fma2(pack2(er[0], er[0]), w, acc[0]);
        acc[1] = fma2(pack2(er[1], er[1]), w, acc[1]);
        acc[2] = fma2(pack2(er[2], er[2]), w, acc[2]);
        acc[3] = fma2(pack2(er[3], er[3]), w, acc[3]);
    }

    float* pf = (float*)g_projP;
#pragma unroll
    for (int r = 0; r < 4; r++) {
        const int n = nb + rg * 4 + r;          // gene index within batch b
        const int chunk = n >> 6;
        const int idx   = n & 63;
        int lane, comp;
        if (chunk < 6) { lane = idx & 31; comp = idx >> 5; }
        else           { lane = idx & 7;  comp = idx >> 3; }
        // float addr of (b, chunk, a=2k, lane, comp); a+1 is +64 floats
        const int fbase = (((b * NCH + chunk) * A_D + 2 * k) * 32 + lane) * 2 + comp;
        float x, y;
        unpack2(acc[r], x, y);
        pf[fbase]      = x;      // a = 2k
        pf[fbase + 64] = y;      // a = 2k+1
    }
}

// ---------------------------------------------------------------------------
// Kernel B (fused). Block = (b, tile of 4 pathways), 256 threads = 8 warps.
// Phase 1: warp -> pathway PAIR (w&1), chunk slots (w>>1): c, c+4.
//          Each lane covers TWO genes packed in f32x2; one proj LDG + one
//          Wb read (pre-duplicated pairs) serve 2 pathways x 64 genes.
//          acc file: 2x8 u64 (each u64 = both genes) = 32 regs.
// Phase 2/3: warp w -> pathway w>>1, half w&1.
//
// SMEM floats:
//   sc    [0, 12800)       scores PT*H*N     (reused as E-chunk 64x200 in ph3)
//   attn  [12800, 14400)   PT*N
//   epsP  [14400, 15424)   PT*128 u64: (ep, ep) duplicated pairs
//   wbP   [15424, 17472)   128*8 u64: (w, w) duplicated pairs
//   sinv  [17472, 17504)
//   bbs   [17504, 17512)
//   idxs  [17512, 17576)   64 ints
// = 70304 bytes -> 3 blocks/SM
// ---------------------------------------------------------------------------
#define SMEM_B_FLOATS 17576
#define SMEM_B_BYTES  (SMEM_B_FLOATS * 4)

extern __shared__ float smemB[];

__global__ __launch_bounds__(256, 3) void kB(
    const int* __restrict__ omc, const int* __restrict__ ptw,
    const float* __restrict__ eg, const float* __restrict__ ept,
    const float* __restrict__ Wb, const float* __restrict__ bb,
    float* __restrict__ out)
{
    float* sc   = smemB;
    float* attn = smemB + 12800;
    u64*   epsP = (u64*)(smemB + 14400);   // PT*128
    u64*   wbP  = (u64*)(smemB + 15424);   // 128*8
    float* sinv = smemB + 17472;
    float* bbs  = smemB + 17504;
    int*   idxs = (int*)(smemB + 17512);

    const int bx   = blockIdx.x;
    const int b    = bx / 50;
    const int pt   = bx - b * 50;
    const int t    = threadIdx.x;
    const int w    = t >> 5;
    const int lane = t & 31;

    // ---- init loads -------------------------------------------------------
    for (int i = t; i < PT * A_D; i += 256) {
        int pl = i >> 7, a = i & 127;
        float v = ept[(long)ptw[pt * PT + pl] * A_D + a];
        epsP[i] = pack2(v, v);
    }
    for (int i = t; i < A_D * H_; i += 256) {
        float v = Wb[i];
        wbP[i] = pack2(v, v);
    }
    if (t < 8) bbs[t] = bb[t];
    __syncthreads();

    // ---- Phase 1: scores, 2 pathways x 64 packed genes per warp -----------
    {
        const int pairI = w & 1;             // pathways 2*pairI, 2*pairI+1
        const u64* epA = epsP + (2 * pairI) * A_D;
        const u64* epB = epA + A_D;
        float* scA = sc + (2 * pairI + 0) * H_ * N_;
        float* scB = sc + (2 * pairI + 1) * H_ * N_;

        for (int c = w >> 1; c < NCH; c += 4) {
            const u64* pp = g_projP + ((b * NCH + c) * A_D) * 32 + lane;

            u64 accA[H_], accB[H_];
#pragma unroll
            for (int h = 0; h < H_; h++) { accA[h] = 0ull; accB[h] = 0ull; }

            u64 pr[4], nxt[4];
#pragma unroll
            for (int j = 0; j < 4; j++) pr[j] = pp[j * 32];

#pragma unroll 1
            for (int a0 = 0; a0 < A_D; a0 += 4) {
                if (a0 < A_D - 4) {
#pragma unroll
                    for (int j = 0; j < 4; j++) nxt[j] = pp[(a0 + 4 + j) * 32];
                }
#pragma unroll
                for (int j = 0; j < 4; j++) {
                    const int a = a0 + j;
                    const u64 prj = pr[j];
                    u64 tA = tanh2(add2(prj, epA[a]));
                    u64 tB = tanh2(add2(prj, epB[a]));
                    const ulonglong2* w4 = (const ulonglong2*)(wbP + a * H_);
                    ulonglong2 w01 = w4[0];
                    accA[0] = fma2(tA, w01.x, accA[0]);
                    accB[0] = fma2(tB, w01.x, accB[0]);
                    accA[1] = fma2(tA, w01.y, accA[1]);
                    accB[1] = fma2(tB, w01.y, accB[1]);
                    ulonglong2 w23 = w4[1];
                    accA[2] = fma2(tA, w23.x, accA[2]);
                    accB[2] = fma2(tB, w23.x, accB[2]);
                    accA[3] = fma2(tA, w23.y, accA[3]);
                    accB[3] = fma2(tB, w23.y, accB[3]);
                    ulonglong2 w45 = w4[2];
                    accA[4] = fma2(tA, w45.x, accA[4]);
                    accB[4] = fma2(tB, w45.x, accB[4]);
                    accA[5] = fma2(tA, w45.y, accA[5]);
                    accB[5] = fma2(tB, w45.y, accB[5]);
                    ulonglong2 w67 = w4[3];
                    accA[6] = fma2(tA, w67.x, accA[6]);
                    accB[6] = fma2(tB, w67.x, accB[6]);
                    accA[7] = fma2(tA, w67.y, accA[7]);
                    accB[7] = fma2(tB, w67.y, accB[7]);
                }
#pragma unroll
                for (int j = 0; j < 4; j++) pr[j] = nxt[j];
            }

            int geneA, geneB;
            bool valid;
            if (c < 6) { geneA = c * 64 + lane; geneB = geneA + 32; valid = true; }
            else       { geneA = 384 + (lane & 7); geneB = geneA + 8; valid = (lane < 8); }
            if (valid) {
#pragma unroll
                for (int h = 0; h < H_; h++) {
                    float xA, yA, xB, yB;
                    unpack2(accA[h], xA, yA);
                    unpack2(accB[h], xB, yB);
                    const float bh = bbs[h];
                    scA[h * N_ + geneA] = xA + bh;
                    scA[h * N_ + geneB] = yA + bh;
                    scB[h * N_ + geneA] = xB + bh;
                    scB[h * N_ + geneB] = yB + bh;
                }
            }
        }
    }
    __syncthreads();

    // ---- Phase 2: softmax over n per head; attn = sum_h -------------------
    const int p    = w >> 1;
    const int half = w & 1;
    const int pg   = pt * PT + p;
    float* scp = sc + p * H_ * N_;
#pragma unroll
    for (int q = 0; q < 4; q++) {
        const int h = half * 4 + q;
        float* row = scp + h * N_;
        float m = -1e30f;
        for (int i = lane; i < N_; i += 32) m = fmaxf(m, row[i]);
#pragma unroll
        for (int o = 16; o; o >>= 1) m = fmaxf(m, __shfl_xor_sync(0xffffffffu, m, o));
        float s = 0.f;
        for (int i = lane; i < N_; i += 32) {
            float e = __expf(row[i] - m);
            row[i] = e;
            s += e;
        }
#pragma unroll
        for (int o = 16; o; o >>= 1) s += __shfl_xor_sync(0xffffffffu, s, o);
        if (lane == 0) sinv[p * H_ + h] = __fdividef(1.f, s);
    }
    __syncthreads();

    {
        float iv[H_];
#pragma unroll
        for (int h = 0; h < H_; h++) iv[h] = sinv[p * H_ + h];
        for (int i = lane; i < 200; i += 32) {
            const int n = half * 200 + i;
            float a = 0.f;
#pragma unroll
            for (int h = 0; h < H_; h++) a = fmaf(scp[h * N_ + n], iv[h], a);
            attn[p * N_ + n] = a;
        }
    }

    // ---- Phase 3: out[b,pg,:] = sum_n attn[n] * E[b,n,:] ------------------
    const u64* eg2 = (const u64*)eg;        // 100 u64 per vocab row
    u64* Es = (u64*)sc;                     // 64 genes x 100 u64 (fits exactly)
    const float* ap = attn + p * N_;
    const int j0 = half * 50;               // this warp's E-slice (u64 units)
    u64 acc0 = 0ull, acc1 = 0ull;

    for (int c = 0; c < 7; c++) {
        const int n0 = c * 64;
        const int cnt = min(64, N_ - n0);
        __syncthreads();                    // protect Es/idxs reuse
        if (t < cnt) idxs[t] = omc[b * N_ + n0 + t];
        __syncthreads();
        for (int i = t; i < cnt * 100; i += 256) {
            int n = i / 100, e2 = i - n * 100;
            Es[n * 100 + e2] = eg2[(long)idxs[n] * 100 + e2];
        }
        __syncthreads();

#pragma unroll 2
        for (int n = 0; n < cnt; n++) {
            float a = ap[n0 + n];
            u64 av = pack2(a, a);
            const u64* er = Es + n * 100;
            acc0 = fma2(er[j0 + lane], av, acc0);
            if (lane < 18) acc1 = fma2(er[j0 + 32 + lane], av, acc1);
        }
    }

    u64* op = (u64*)out + (long)(b * P_ + pg) * 100;
    op[j0 + lane] = acc0;
    if (lane < 18) op[j0 + 32 + lane] = acc1;
}

// ---------------------------------------------------------------------------
extern "C" void kernel_launch(void* const* d_in, const int* in_sizes, int n_in,
                              void* d_out, int out_size)
{
    const int*   omc = (const int*)  d_in[0];
    const int*   ptw = (const int*)  d_in[1];
    const float* eg  = (const float*)d_in[2];
    const float* ept = (const float*)d_in[3];
    const float* W0  = (const float*)d_in[4];
    const float* b0  = (const float*)d_in[5];
    const float* Wb  = (const float*)d_in[6];
    const float* bb  = (const float*)d_in[7];
    float* out = (float*)d_out;

    kA<<<(B_ * N_) / 8, 128>>>(omc, eg, W0, b0);

    cudaFuncSetAttribute(kB, cudaFuncAttributeMaxDynamicSharedMemorySize,
                         SMEM_B_BYTES);
    kB<<<B_ * (P_ / PT), 256, SMEM_B_BYTES>>>(omc, ptw, eg, ept, Wb, bb, out);
}

// round 7
// speedup vs baseline: 6.3635x; 1.1111x over previous
#include <cuda_runtime.h>

#define B_    16
#define N_    400
#define P_    200
#define E_D   200
#define A_D   128
#define H_    8
#define PT    4      // pathways per block in kernel B
#define NCH   7      // gene chunks of 64 (6 full + 1 partial of 16)

typedef unsigned long long u64;

// proj scratch: ulonglong2 at ((b*NCH + c)*64 + k)*32 + lane =
//   { u64(prj[gLo][2k],  prj[gHi][2k]),  u64(prj[gLo][2k+1], prj[gHi][2k+1]) }
// where gLo = c*64+lane, gHi = gLo+32 (c<6); chunk 6: lane<8, gLo=384+lane, gHi=gLo+8.
__device__ ulonglong2 g_projP[B_ * NCH * 64 * 32];

__device__ __forceinline__ u64 pack2(float x, float y) {
    u64 r; asm("mov.b64 %0, {%1, %2};" : "=l"(r) : "f"(x), "f"(y)); return r;
}
__device__ __forceinline__ void unpack2(u64 v, float& x, float& y) {
    asm("mov.b64 {%0, %1}, %2;" : "=f"(x), "=f"(y) : "l"(v));
}
__device__ __forceinline__ u64 fma2(u64 a, u64 b, u64 c) {
    u64 d; asm("fma.rn.f32x2 %0, %1, %2, %3;" : "=l"(d) : "l"(a), "l"(b), "l"(c)); return d;
}
__device__ __forceinline__ u64 add2(u64 a, u64 b) {
    u64 d; asm("add.rn.f32x2 %0, %1, %2;" : "=l"(d) : "l"(a), "l"(b)); return d;
}
__device__ __forceinline__ float tanh_ap(float x) {
    float y; asm("tanh.approx.f32 %0, %1;" : "=f"(y) : "f"(x)); return y;
}
__device__ __forceinline__ u64 tanh2(u64 v) {
    float x, y; unpack2(v, x, y);
    return pack2(tanh_ap(x), tanh_ap(y));
}

// ---------------------------------------------------------------------------
// Kernel A: proj = emb_gene[omc] @ W0 + b0, scattered into gene-paired layout.
// Block = 8 rows (one b). t = (rg, k): k = a-pair 0..63, rg = row-group 0..1.
// ---------------------------------------------------------------------------
__global__ __launch_bounds__(128) void kA(
    const int* __restrict__ omc, const float* __restrict__ eg,
    const float* __restrict__ W0, const float* __restrict__ b0)
{
    __shared__ float EsT[E_D * 8];   // [e][r]
    __shared__ int idxs[8];
    const int R0 = blockIdx.x * 8;
    const int b  = R0 / N_;
    const int nb = R0 - b * N_;
    const int t  = threadIdx.x;

    if (t < 8) idxs[t] = omc[R0 + t];
    __syncthreads();
    for (int i = t; i < 8 * E_D; i += 128) {
        int r = i / E_D, e = i - r * E_D;
        EsT[e * 8 + r] = eg[(long)idxs[r] * E_D + e];
    }
    __syncthreads();

    const int k  = t & 63;           // a-pair: a = 2k, 2k+1
    const int rg = t >> 6;           // row group (4 rows each)
    const u64* W2 = (const u64*)W0;  // [e][64] pairs
    const u64  bias = ((const u64*)b0)[k];

    u64 acc[4];
#pragma unroll
    for (int r = 0; r < 4; r++) acc[r] = bias;

#pragma unroll 4
    for (int e = 0; e < E_D; e++) {
        u64 w = W2[e * 64 + k];
        const float* er = EsT + e * 8 + rg * 4;
        acc[0] = fma2(pack2(er[0], er[0]), w, acc[0]);
        acc[1] = fma2(pack2(er[1], er[1]), w, acc[1]);
        acc[2] = fma2(pack2(er[2], er[2]), w, acc[2]);
        acc[3] = fma2(pack2(er[3], er[3]), w, acc[3]);
    }

    float* pf = (float*)g_projP;
#pragma unroll
    for (int r = 0; r < 4; r++) {
        const int n = nb + rg * 4 + r;          // gene index within batch b
        const int chunk = n >> 6;
        const int idx   = n & 63;
        int lane, comp;
        if (chunk < 6) { lane = idx & 31; comp = idx >> 5; }
        else           { lane = idx & 7;  comp = idx >> 3; }
        // float layout of ulonglong2 cell: {aLo.gLo, aLo.gHi, aHi.gLo, aHi.gHi}
        const int fbase = (((b * NCH + chunk) * 64 + k) * 32 + lane) * 4 + comp;
        float x, y;
        unpack2(acc[r], x, y);
        pf[fbase]     = x;      // a = 2k
        pf[fbase + 2] = y;      // a = 2k+1
    }
}

// ---------------------------------------------------------------------------
// Kernel B (fused). Block = (b, tile of 4 pathways), 256 threads = 8 warps.
// Phase 1: warp -> pathway PAIR (w&1), chunk slots (w>>1): c, c+4.
//          Lane covers TWO genes packed in f32x2; one LDG.128 = 2 a-steps;
//          ep as ONE LDS.128 per a (dupA, dupB); Wb pre-duplicated LDS.128.
// Phase 2/3: warp w -> pathway w>>1, half w&1.
//
// SMEM floats:
//   sc    [0, 12800)       scores PT*H*N     (reused as E-chunk 64x200 in ph3)
//   attn  [12800, 14400)   PT*N
//   epsQ  [14400, 15424)   2 groups x 128 a x {dupA u64, dupB u64} (16B recs)
//   wbP   [15424, 17472)   128*8 u64: (w, w) duplicated pairs
//   sinv  [17472, 17504)
//   bbs   [17504, 17512)
//   idxs  [17512, 17576)   64 ints
// = 70304 bytes -> 3 blocks/SM (also the 80-reg ceiling)
// ---------------------------------------------------------------------------
#define SMEM_B_FLOATS 17576
#define SMEM_B_BYTES  (SMEM_B_FLOATS * 4)

extern __shared__ float smemB[];

__global__ __launch_bounds__(256, 3) void kB(
    const int* __restrict__ omc, const int* __restrict__ ptw,
    const float* __restrict__ eg, const float* __restrict__ ept,
    const float* __restrict__ Wb, const float* __restrict__ bb,
    float* __restrict__ out)
{
    float* sc   = smemB;
    float* attn = smemB + 12800;
    ulonglong2* epsQ = (ulonglong2*)(smemB + 14400);  // [group*128 + a]
    u64*   wbP  = (u64*)(smemB + 15424);              // 128*8
    float* sinv = smemB + 17472;
    float* bbs  = smemB + 17504;
    int*   idxs = (int*)(smemB + 17512);

    const int bx   = blockIdx.x;
    const int b    = bx / 50;
    const int pt   = bx - b * 50;
    const int t    = threadIdx.x;
    const int w    = t >> 5;
    const int lane = t & 31;

    // ---- init loads -------------------------------------------------------
    // epsQ[g*128 + a] = { (epA[a], epA[a]), (epB[a], epB[a]) } for pathways 2g, 2g+1
    {
        float* ef = (float*)epsQ;
        for (int i = t; i < 1024; i += 256) {
            int g  = i >> 9;            // group 0..1
            int a  = (i >> 2) & 127;
            int c4 = i & 3;             // 0,1 -> dupA; 2,3 -> dupB
            int pl = g * 2 + (c4 >> 1);
            ef[(g * 128 + a) * 4 + c4] = ept[(long)ptw[pt * PT + pl] * A_D + a];
        }
    }
    for (int i = t; i < A_D * H_; i += 256) {
        float v = Wb[i];
        wbP[i] = pack2(v, v);
    }
    if (t < 8) bbs[t] = bb[t];
    __syncthreads();

    // ---- Phase 1: scores, 2 pathways x 64 packed genes per warp -----------
    {
        const int pairI = w & 1;             // pathways 2*pairI, 2*pairI+1
        const ulonglong2* epq = epsQ + pairI * 128;
        float* scA = sc + (2 * pairI + 0) * H_ * N_;
        float* scB = sc + (2 * pairI + 1) * H_ * N_;

        for (int c = w >> 1; c < NCH; c += 4) {
            const ulonglong2* pp = g_projP + ((b * NCH + c) * 64) * 32 + lane;

            u64 accA[H_], accB[H_];
#pragma unroll
            for (int h = 0; h < H_; h++) { accA[h] = 0ull; accB[h] = 0ull; }

            ulonglong2 pr0 = pp[0];
            ulonglong2 pr1 = pp[32];
            ulonglong2 nx0, nx1;

#pragma unroll 1
            for (int k0 = 0; k0 < 64; k0 += 2) {
                if (k0 < 62) {
                    nx0 = pp[(k0 + 2) * 32];
                    nx1 = pp[(k0 + 3) * 32];
                }
#pragma unroll
                for (int j = 0; j < 4; j++) {
                    const int a = k0 * 2 + j;
                    const u64 prj = (j == 0) ? pr0.x : (j == 1) ? pr0.y
                                  : (j == 2) ? pr1.x : pr1.y;
                    ulonglong2 e2 = epq[a];
                    u64 tA = tanh2(add2(prj, e2.x));
                    u64 tB = tanh2(add2(prj, e2.y));
                    const ulonglong2* w4 = (const ulonglong2*)(wbP + a * H_);
                    ulonglong2 w01 = w4[0];
                    accA[0] = fma2(tA, w01.x, accA[0]);
                    accB[0] = fma2(tB, w01.x, accB[0]);
                    accA[1] = fma2(tA, w01.y, accA[1]);
                    accB[1] = fma2(tB, w01.y, accB[1]);
                    ulonglong2 w23 = w4[1];
                    accA[2] = fma2(tA, w23.x, accA[2]);
                    accB[2] = fma2(tB, w23.x, accB[2]);
                    accA[3] = fma2(tA, w23.y, accA[3]);
                    accB[3] = fma2(tB, w23.y, accB[3]);
                    ulonglong2 w45 = w4[2];
                    accA[4] = fma2(tA, w45.x, accA[4]);
                    accB[4] = fma2(tB, w45.x, accB[4]);
                    accA[5] = fma2(tA, w45.y, accA[5]);
                    accB[5] = fma2(tB, w45.y, accB[5]);
                    ulonglong2 w67 = w4[3];
                    accA[6] = fma2(tA, w67.x, accA[6]);
                    accB[6] = fma2(tB, w67.x, accB[6]);
                    accA[7] = fma2(tA, w67.y, accA[7]);
                    accB[7] = fma2(tB, w67.y, accB[7]);
                }
                pr0 = nx0;
                pr1 = nx1;
            }

            int geneA, geneB;
            bool valid;
            if (c < 6) { geneA = c * 64 + lane; geneB = geneA + 32; valid = true; }
            else       { geneA = 384 + (lane & 7); geneB = geneA + 8; valid = (lane < 8); }
            if (valid) {
#pragma unroll
                for (int h = 0; h < H_; h++) {
                    float xA, yA, xB, yB;
                    unpack2(accA[h], xA, yA);
                    unpack2(accB[h], xB, yB);
                    const float bh = bbs[h];
                    scA[h * N_ + geneA] = xA + bh;
                    scA[h * N_ + geneB] = yA + bh;
                    scB[h * N_ + geneA] = xB + bh;
                    scB[h * N_ + geneB] = yB + bh;
                }
            }
        }
    }
    __syncthreads();

    // ---- Phase 2: softmax over n per head; attn = sum_h -------------------
    const int p    = w >> 1;
    const int half = w & 1;
    const int pg   = pt * PT + p;
    float* scp = sc + p * H_ * N_;
#pragma unroll
    for (int q = 0; q < 4; q++) {
        const int h = half * 4 + q;
        float* row = scp + h * N_;
        float m = -1e30f;
        for (int i = lane; i < N_; i += 32) m = fmaxf(m, row[i]);
#pragma unroll
        for (int o = 16; o; o >>= 1) m = fmaxf(m, __shfl_xor_sync(0xffffffffu, m, o));
        float s = 0.f;
        for (int i = lane; i < N_; i += 32) {
            float e = __expf(row[i] - m);
            row[i] = e;
            s += e;
        }
#pragma unroll
        for (int o = 16; o; o >>= 1) s += __shfl_xor_sync(0xffffffffu, s, o);
        if (lane == 0) sinv[p * H_ + h] = __fdividef(1.f, s);
    }
    __syncthreads();

    {
        float iv[H_];
#pragma unroll
        for (int h = 0; h < H_; h++) iv[h] = sinv[p * H_ + h];
        for (int i = lane; i < 200; i += 32) {
            const int n = half * 200 + i;
            float a = 0.f;
#pragma unroll
            for (int h = 0; h < H_; h++) a = fmaf(scp[h * N_ + n], iv[h], a);
            attn[p * N_ + n] = a;
        }
    }

    // ---- Phase 3: out[b,pg,:] = sum_n attn[n] * E[b,n,:] ------------------
    const ulonglong2* eg4 = (const ulonglong2*)eg;   // 50 per vocab row
    ulonglong2* Es4 = (ulonglong2*)sc;               // 64 genes x 50 recs
    const float* ap = attn + p * N_;
    const int j0 = half * 50;                        // E-slice in u64 units
    u64 acc0 = 0ull, acc1 = 0ull;

    for (int c = 0; c < 7; c++) {
        const int n0 = c * 64;
        const int cnt = min(64, N_ - n0);
        __syncthreads();                    // protect Es/idxs reuse
        if (t < cnt) idxs[t] = omc[b * N_ + n0 + t];
        __syncthreads();
        for (int i = t; i < cnt * 50; i += 256) {
            int n = i / 50, e4 = i - n * 50;
            Es4[n * 50 + e4] = eg4[(long)idxs[n] * 50 + e4];
        }
        __syncthreads();

        const u64* Es = (const u64*)Es4;
#pragma unroll 2
        for (int n = 0; n < cnt; n++) {
            float a = ap[n0 + n];
            u64 av = pack2(a, a);
            const u64* er = Es + n * 100;
            acc0 = fma2(er[j0 + lane], av, acc0);
            if (lane < 18) acc1 = fma2(er[j0 + 32 + lane], av, acc1);
        }
    }

    u64* op = (u64*)out + (long)(b * P_ + pg) * 100;
    op[j0 + lane] = acc0;
    if (lane < 18) op[j0 + 32 + lane] = acc1;
}

// ---------------------------------------------------------------------------
extern "C" void kernel_launch(void* const* d_in, const int* in_sizes, int n_in,
                              void* d_out, int out_size)
{
    const int*   omc = (const int*)  d_in[0];
    const int*   ptw = (const int*)  d_in[1];
    const float* eg  = (const float*)d_in[2];
    const float* ept = (const float*)d_in[3];
    const float* W0  = (const float*)d_in[4];
    const float* b0  = (const float*)d_in[5];
    const float* Wb  = (const float*)d_in[6];
    const float* bb  = (const float*)d_in[7];
    float* out = (float*)d_out;

    kA<<<(B_ * N_) / 8, 128>>>(omc, eg, W0, b0);

    cudaFuncSetAttribute(kB, cudaFuncAttributeMaxDynamicSharedMemorySize,
                         SMEM_B_BYTES);
    kB<<<B_ * (P_ / PT), 256, SMEM_B_BYTES>>>(omc, ptw, eg, ept, Wb, bb, out);
}

// round 8
// speedup vs baseline: 6.3897x; 1.0041x over previous
#include <cuda_runtime.h>

#define B_    16
#define N_    400
#define P_    200
#define E_D   200
#define A_D   128
#define H_    8
#define PT    4      // pathways per block in kernel B
#define NCH   7      // gene chunks of 64 (6 full + 1 partial of 16)

typedef unsigned long long u64;

// proj scratch: ulonglong2 at ((b*NCH + c)*64 + k)*32 + lane =
//   { u64(prj[gLo][2k],  prj[gHi][2k]),  u64(prj[gLo][2k+1], prj[gHi][2k+1]) }
// where gLo = c*64+lane, gHi = gLo+32 (c<6); chunk 6: lane<8, gLo=384+lane, gHi=gLo+8.
__device__ ulonglong2 g_projP[B_ * NCH * 64 * 32];

__device__ __forceinline__ u64 pack2(float x, float y) {
    u64 r; asm("mov.b64 %0, {%1, %2};" : "=l"(r) : "f"(x), "f"(y)); return r;
}
__device__ __forceinline__ void unpack2(u64 v, float& x, float& y) {
    asm("mov.b64 {%0, %1}, %2;" : "=f"(x), "=f"(y) : "l"(v));
}
__device__ __forceinline__ u64 fma2(u64 a, u64 b, u64 c) {
    u64 d; asm("fma.rn.f32x2 %0, %1, %2, %3;" : "=l"(d) : "l"(a), "l"(b), "l"(c)); return d;
}
__device__ __forceinline__ u64 add2(u64 a, u64 b) {
    u64 d; asm("add.rn.f32x2 %0, %1, %2;" : "=l"(d) : "l"(a), "l"(b)); return d;
}
__device__ __forceinline__ float tanh_ap(float x) {
    float y; asm("tanh.approx.f32 %0, %1;" : "=f"(y) : "f"(x)); return y;
}
__device__ __forceinline__ u64 tanh2(u64 v) {
    float x, y; unpack2(v, x, y);
    return pack2(tanh_ap(x), tanh_ap(y));
}

// ---------------------------------------------------------------------------
// Kernel A: proj = emb_gene[omc] @ W0 + b0, scattered into gene-paired layout.
// ---------------------------------------------------------------------------
__global__ __launch_bounds__(128) void kA(
    const int* __restrict__ omc, const float* __restrict__ eg,
    const float* __restrict__ W0, const float* __restrict__ b0)
{
    __shared__ float EsT[E_D * 8];   // [e][r]
    __shared__ int idxs[8];
    const int R0 = blockIdx.x * 8;
    const int b  = R0 / N_;
    const int nb = R0 - b * N_;
    const int t  = threadIdx.x;

    if (t < 8) idxs[t] = omc[R0 + t];
    __syncthreads();
    for (int i = t; i < 8 * E_D; i += 128) {
        int r = i / E_D, e = i - r * E_D;
        EsT[e * 8 + r] = eg[(long)idxs[r] * E_D + e];
    }
    __syncthreads();

    const int k  = t & 63;           // a-pair: a = 2k, 2k+1
    const int rg = t >> 6;           // row group (4 rows each)
    const u64* W2 = (const u64*)W0;  // [e][64] pairs
    const u64  bias = ((const u64*)b0)[k];

    u64 acc[4];
#pragma unroll
    for (int r = 0; r < 4; r++) acc[r] = bias;

#pragma unroll 4
    for (int e = 0; e < E_D; e++) {
        u64 w = W2[e * 64 + k];
        const float* er = EsT + e * 8 + rg * 4;
        acc[0] = fma2(pack2(er[0], er[0]), w, acc[0]);
        acc[1] = fma2(pack2(er[1], er[1]), w, acc[1]);
        acc[2] = fma2(pack2(er[2], er[2]), w, acc[2]);
        acc[3] = fma2(pack2(er[3], er[3]), w, acc[3]);
    }

    float* pf = (float*)g_projP;
#pragma unroll
    for (int r = 0; r < 4; r++) {
        const int n = nb + rg * 4 + r;          // gene index within batch b
        const int chunk = n >> 6;
        const int idx   = n & 63;
        int lane, comp;
        if (chunk < 6) { lane = idx & 31; comp = idx >> 5; }
        else           { lane = idx & 7;  comp = idx >> 3; }
        // float layout of ulonglong2 cell: {aLo.gLo, aLo.gHi, aHi.gLo, aHi.gHi}
        const int fbase = (((b * NCH + chunk) * 64 + k) * 32 + lane) * 4 + comp;
        float x, y;
        unpack2(acc[r], x, y);
        pf[fbase]     = x;      // a = 2k
        pf[fbase + 2] = y;      // a = 2k+1
    }
}

// ---------------------------------------------------------------------------
// Kernel B (fused). Block = (b, tile of 4 pathways), 256 threads = 8 warps.
// Phase 1: warp -> pathway PAIR (w&1), chunk slots (w>>1): c, c+4.
//          Inner loop: all smem/global accesses via running byte-pointers +
//          compile-time immediates (3 pointer bumps/iter instead of ~20 IMAD).
// Phase 2/3: warp w -> pathway w>>1, half w&1.
//
// SMEM floats:
//   sc    [0, 12800)       scores PT*H*N     (reused as E-chunk 64x200 in ph3)
//   attn  [12800, 14400)   PT*N
//   epsQ  [14400, 15424)   2 groups x 128 a x {dupA u64, dupB u64} (16B recs)
//   wbP   [15424, 17472)   128*8 u64: (w, w) duplicated pairs
//   sinv  [17472, 17504)
//   bbs   [17504, 17512)
//   idxs  [17512, 17576)   64 ints
// = 70304 bytes -> 3 blocks/SM (also the ~85-reg ceiling)
// ---------------------------------------------------------------------------
#define SMEM_B_FLOATS 17576
#define SMEM_B_BYTES  (SMEM_B_FLOATS * 4)

extern __shared__ float smemB[];

__global__ __launch_bounds__(256, 3) void kB(
    const int* __restrict__ omc, const int* __restrict__ ptw,
    const float* __restrict__ eg, const float* __restrict__ ept,
    const float* __restrict__ Wb, const float* __restrict__ bb,
    float* __restrict__ out)
{
    float* sc   = smemB;
    float* attn = smemB + 12800;
    ulonglong2* epsQ = (ulonglong2*)(smemB + 14400);  // [group*128 + a]
    u64*   wbP  = (u64*)(smemB + 15424);              // 128*8
    float* sinv = smemB + 17472;
    float* bbs  = smemB + 17504;
    int*   idxs = (int*)(smemB + 17512);

    const int bx   = blockIdx.x;
    const int b    = bx / 50;
    const int pt   = bx - b * 50;
    const int t    = threadIdx.x;
    const int w    = t >> 5;
    const int lane = t & 31;

    // ---- init loads -------------------------------------------------------
    // epsQ[g*128 + a] = { (epA[a], epA[a]), (epB[a], epB[a]) } for pathways 2g, 2g+1
    {
        float* ef = (float*)epsQ;
        for (int i = t; i < 1024; i += 256) {
            int g  = i >> 9;            // group 0..1
            int a  = (i >> 2) & 127;
            int c4 = i & 3;             // 0,1 -> dupA; 2,3 -> dupB
            int pl = g * 2 + (c4 >> 1);
            ef[(g * 128 + a) * 4 + c4] = ept[(long)ptw[pt * PT + pl] * A_D + a];
        }
    }
    for (int i = t; i < A_D * H_; i += 256) {
        float v = Wb[i];
        wbP[i] = pack2(v, v);
    }
    if (t < 8) bbs[t] = bb[t];
    __syncthreads();

    // ---- Phase 1: scores, 2 pathways x 64 packed genes per warp -----------
    {
        const int pairI = w & 1;             // pathways 2*pairI, 2*pairI+1
        float* scA = sc + (2 * pairI + 0) * H_ * N_;
        float* scB = sc + (2 * pairI + 1) * H_ * N_;

        for (int c = w >> 1; c < NCH; c += 4) {
            u64 accA[H_], accB[H_];
#pragma unroll
            for (int h = 0; h < H_; h++) { accA[h] = 0ull; accB[h] = 0ull; }

            // running byte pointers (imm-offset addressing inside the loop)
            const char* ppB = (const char*)(g_projP + ((b * NCH + c) * 64) * 32 + lane);
            const char* epB = (const char*)(epsQ + pairI * 128);
            const char* wbB = (const char*)wbP;

            ulonglong2 pr0 = *(const ulonglong2*)ppB;
            ulonglong2 pr1 = *(const ulonglong2*)(ppB + 512);
            ulonglong2 nx0, nx1;
            ppB += 1024;

#pragma unroll 1
            for (int it = 0; it < 32; it++) {
                if (it < 31) {
                    nx0 = *(const ulonglong2*)ppB;
                    nx1 = *(const ulonglong2*)(ppB + 512);
                }
#pragma unroll
                for (int j = 0; j < 4; j++) {
                    const u64 prj = (j == 0) ? pr0.x : (j == 1) ? pr0.y
                                  : (j == 2) ? pr1.x : pr1.y;
                    ulonglong2 e2 = *(const ulonglong2*)(epB + j * 16);
                    u64 tA = tanh2(add2(prj, e2.x));
                    u64 tB = tanh2(add2(prj, e2.y));
                    const ulonglong2* w4 = (const ulonglong2*)(wbB + j * 64);
                    ulonglong2 w01 = w4[0];
                    accA[0] = fma2(tA, w01.x, accA[0]);
                    accB[0] = fma2(tB, w01.x, accB[0]);
                    accA[1] = fma2(tA, w01.y, accA[1]);
                    accB[1] = fma2(tB, w01.y, accB[1]);
                    ulonglong2 w23 = w4[1];
                    accA[2] = fma2(tA, w23.x, accA[2]);
                    accB[2] = fma2(tB, w23.x, accB[2]);
                    accA[3] = fma2(tA, w23.y, accA[3]);
                    accB[3] = fma2(tB, w23.y, accB[3]);
                    ulonglong2 w45 = w4[2];
                    accA[4] = fma2(tA, w45.x, accA[4]);
                    accB[4] = fma2(tB, w45.x, accB[4]);
                    accA[5] = fma2(tA, w45.y, accA[5]);
                    accB[5] = fma2(tB, w45.y, accB[5]);
                    ulonglong2 w67 = w4[3];
                    accA[6] = fma2(tA, w67.x, accA[6]);
                    accB[6] = fma2(tB, w67.x, accB[6]);
                    accA[7] = fma2(tA, w67.y, accA[7]);
                    accB[7] = fma2(tB, w67.y, accB[7]);
                }
                pr0 = nx0;
                pr1 = nx1;
                ppB += 1024;
                epB += 64;
                wbB += 256;
            }

            int geneA, geneB;
            bool valid;
            if (c < 6) { geneA = c * 64 + lane; geneB = geneA + 32; valid = true; }
            else       { geneA = 384 + (lane & 7); geneB = geneA + 8; valid = (lane < 8); }
            if (valid) {
#pragma unroll
                for (int h = 0; h < H_; h++) {
                    float xA, yA, xB, yB;
                    unpack2(accA[h], xA, yA);
                    unpack2(accB[h], xB, yB);
                    const float bh = bbs[h];
                    scA[h * N_ + geneA] = xA + bh;
                    scA[h * N_ + geneB] = yA + bh;
                    scB[h * N_ + geneA] = xB + bh;
                    scB[h * N_ + geneB] = yB + bh;
                }
            }
        }
    }
    __syncthreads();

    // ---- Phase 2: softmax over n per head; attn = sum_h -------------------
    const int p    = w >> 1;
    const int half = w & 1;
    const int pg   = pt * PT + p;
    float* scp = sc + p * H_ * N_;
#pragma unroll
    for (int q = 0; q < 4; q++) {
        const int h = half * 4 + q;
        float* row = scp + h * N_;
        float m = -1e30f;
        for (int i = lane; i < N_; i += 32) m = fmaxf(m, row[i]);
#pragma unroll
        for (int o = 16; o; o >>= 1) m = fmaxf(m, __shfl_xor_sync(0xffffffffu, m, o));
        float s = 0.f;
        for (int i = lane; i < N_; i += 32) {
            float e = __expf(row[i] - m);
            row[i] = e;
            s += e;
        }
#pragma unroll
        for (int o = 16; o; o >>= 1) s += __shfl_xor_sync(0xffffffffu, s, o);
        if (lane == 0) sinv[p * H_ + h] = __fdividef(1.f, s);
    }
    __syncthreads();

    {
        float iv[H_];
#pragma unroll
        for (int h = 0; h < H_; h++) iv[h] = sinv[p * H_ + h];
        for (int i = lane; i < 200; i += 32) {
            const int n = half * 200 + i;
            float a = 0.f;
#pragma unroll
            for (int h = 0; h < H_; h++) a = fmaf(scp[h * N_ + n], iv[h], a);
            attn[p * N_ + n] = a;
        }
    }

    // ---- Phase 3: out[b,pg,:] = sum_n attn[n] * E[b,n,:] ------------------
    const ulonglong2* eg4 = (const ulonglong2*)eg;   // 50 per vocab row
    ulonglong2* Es4 = (ulonglong2*)sc;               // 64 genes x 50 recs
    const float* ap = attn + p * N_;
    const int j0 = half * 50;                        // E-slice in u64 units
    u64 acc0 = 0ull, acc1 = 0ull;

    for (int c = 0; c < 7; c++) {
        const int n0 = c * 64;
        const int cnt = min(64, N_ - n0);
        __syncthreads();                    // protect Es/idxs reuse
        if (t < cnt) idxs[t] = omc[b * N_ + n0 + t];
        __syncthreads();
        for (int i = t; i < cnt * 50; i += 256) {
            int n = i / 50, e4 = i - n * 50;
            Es4[n * 50 + e4] = eg4[(long)idxs[n] * 50 + e4];
        }
        __syncthreads();

        const u64* Es = (const u64*)Es4;
#pragma unroll 2
        for (int n = 0; n < cnt; n++) {
            float a = ap[n0 + n];
            u64 av = pack2(a, a);
            const u64* er = Es + n * 100;
            acc0 = fma2(er[j0 + lane], av, acc0);
            if (lane < 18) acc1 = fma2(er[j0 + 32 + lane], av, acc1);
        }
    }

    u64* op = (u64*)out + (long)(b * P_ + pg) * 100;
    op[j0 + lane] = acc0;
    if (lane < 18) op[j0 + 32 + lane] = acc1;
}

// ---------------------------------------------------------------------------
extern "C" void kernel_launch(void* const* d_in, const int* in_sizes, int n_in,
                              void* d_out, int out_size)
{
    const int*   omc = (const int*)  d_in[0];
    const int*   ptw = (const int*)  d_in[1];
    const float* eg  = (const float*)d_in[2];
    const float* ept = (const float*)d_in[3];
    const float* W0  = (const float*)d_in[4];
    const float* b0  = (const float*)d_in[5];
    const float* Wb  = (const float*)d_in[6];
    const float* bb  = (const float*)d_in[7];
    float* out = (float*)d_out;

    kA<<<(B_ * N_) / 8, 128>>>(omc, eg, W0, b0);

    cudaFuncSetAttribute(kB, cudaFuncAttributeMaxDynamicSharedMemorySize,
                         SMEM_B_BYTES);
    kB<<<B_ * (P_ / PT), 256, SMEM_B_BYTES>>>(omc, ptw, eg, ept, Wb, bb, out);
}

// round 9
// speedup vs baseline: 6.5077x; 1.0185x over previous
#include <cuda_runtime.h>

#define B_    16
#define N_    400
#define P_    200
#define E_D   200
#define A_D   128
#define H_    8
#define PT    4      // pathways per block in kernel B
#define NCH   7      // gene chunks of 64 (6 full + 1 partial of 16)

typedef unsigned long long u64;

// proj scratch: ulonglong2 at ((b*NCH + c)*64 + k)*32 + lane =
//   { u64(prj[gLo][2k],  prj[gHi][2k]),  u64(prj[gLo][2k+1], prj[gHi][2k+1]) }
// gLo = c*64+lane, gHi = gLo+32 (c<6); chunk 6: lane<8, gLo=384+lane, gHi=gLo+8.
__device__ ulonglong2 g_projP[B_ * NCH * 64 * 32];

__device__ __forceinline__ u64 pack2(float x, float y) {
    u64 r; asm("mov.b64 %0, {%1, %2};" : "=l"(r) : "f"(x), "f"(y)); return r;
}
__device__ __forceinline__ void unpack2(u64 v, float& x, float& y) {
    asm("mov.b64 {%0, %1}, %2;" : "=f"(x), "=f"(y) : "l"(v));
}
__device__ __forceinline__ u64 fma2(u64 a, u64 b, u64 c) {
    u64 d; asm("fma.rn.f32x2 %0, %1, %2, %3;" : "=l"(d) : "l"(a), "l"(b), "l"(c)); return d;
}
__device__ __forceinline__ u64 add2(u64 a, u64 b) {
    u64 d; asm("add.rn.f32x2 %0, %1, %2;" : "=l"(d) : "l"(a), "l"(b)); return d;
}
__device__ __forceinline__ float tanh_ap(float x) {
    float y; asm("tanh.approx.f32 %0, %1;" : "=f"(y) : "f"(x)); return y;
}
__device__ __forceinline__ u64 tanh2(u64 v) {
    float x, y; unpack2(v, x, y);
    return pack2(tanh_ap(x), tanh_ap(y));
}

// ---------------------------------------------------------------------------
// Kernel A: proj = emb_gene[omc] @ W0 + b0, scattered into gene-paired layout.
// ---------------------------------------------------------------------------
__global__ __launch_bounds__(128) void kA(
    const int* __restrict__ omc, const float* __restrict__ eg,
    const float* __restrict__ W0, const float* __restrict__ b0)
{
    __shared__ float EsT[E_D * 8];   // [e][r]
    __shared__ int idxs[8];
    const int R0 = blockIdx.x * 8;
    const int b  = R0 / N_;
    const int nb = R0 - b * N_;
    const int t  = threadIdx.x;

    if (t < 8) idxs[t] = omc[R0 + t];
    __syncthreads();
    for (int i = t; i < 8 * E_D; i += 128) {
        int r = i / E_D, e = i - r * E_D;
        EsT[e * 8 + r] = eg[(long)idxs[r] * E_D + e];
    }
    __syncthreads();

    const int k  = t & 63;           // a-pair: a = 2k, 2k+1
    const int rg = t >> 6;           // row group (4 rows each)
    const u64* W2 = (const u64*)W0;  // [e][64] pairs
    const u64  bias = ((const u64*)b0)[k];

    u64 acc[4];
#pragma unroll
    for (int r = 0; r < 4; r++) acc[r] = bias;

#pragma unroll 4
    for (int e = 0; e < E_D; e++) {
        u64 w = W2[e * 64 + k];
        const float* er = EsT + e * 8 + rg * 4;
        acc[0] = fma2(pack2(er[0], er[0]), w, acc[0]);
        acc[1] = fma2(pack2(er[1], er[1]), w, acc[1]);
        acc[2] = fma2(pack2(er[2], er[2]), w, acc[2]);
        acc[3] = fma2(pack2(er[3], er[3]), w, acc[3]);
    }

    float* pf = (float*)g_projP;
#pragma unroll
    for (int r = 0; r < 4; r++) {
        const int n = nb + rg * 4 + r;          // gene index within batch b
        const int chunk = n >> 6;
        const int idx   = n & 63;
        int lane, comp;
        if (chunk < 6) { lane = idx & 31; comp = idx >> 5; }
        else           { lane = idx & 7;  comp = idx >> 3; }
        // float layout of ulonglong2 cell: {aLo.gLo, aLo.gHi, aHi.gLo, aHi.gHi}
        const int fbase = (((b * NCH + chunk) * 64 + k) * 32 + lane) * 4 + comp;
        float x, y;
        unpack2(acc[r], x, y);
        pf[fbase]     = x;      // a = 2k
        pf[fbase + 2] = y;      // a = 2k+1
    }
}

// ---------------------------------------------------------------------------
// Kernel B (fused). Block = (b, tile of 4 pathways), 256 threads = 8 warps.
// Phase 1: warp -> pathway PAIR (w&1), chunk slots (w>>1): c, c+4.
//          SOFTWARE-PIPELINED stages (1 stage = 1 LDG.128 = 2 a-values):
//            - tanh computed one stage ahead of its FMA consumption
//            - proj LDG issued two stages ahead
//          so MUFU/LDS latency overlaps the 32-fma2 block of stage s.
// Phase 2/3: warp w -> pathway w>>1, half w&1.
//
// SMEM floats:
//   sc    [0, 12800)       scores PT*H*N     (reused as E-chunk 64x200 in ph3)
//   attn  [12800, 14400)   PT*N
//   epsQ  [14400, 15424)   2 groups x 128 a x {dupA u64, dupB u64} (16B recs)
//   wbP   [15424, 17472)   128*8 u64: (w, w) duplicated pairs
//   sinv  [17472, 17504)
//   bbs   [17504, 17512)
//   idxs  [17512, 17576)   64 ints
// = 70304 bytes -> 3 blocks/SM (~85-reg ceiling)
// ---------------------------------------------------------------------------
#define SMEM_B_FLOATS 17576
#define SMEM_B_BYTES  (SMEM_B_FLOATS * 4)

extern __shared__ float smemB[];

// FMA block for one stage: T0/T1 = pathA/pathB (a even), T2/T3 = (a odd).
#define STAGE_FMA(wbB, T0, T1, T2, T3)                                  \
    do {                                                                \
        const ulonglong2* w4e = (const ulonglong2*)(wbB);               \
        ulonglong2 wA = w4e[0];                                         \
        accA[0] = fma2(T0, wA.x, accA[0]);                              \
        accB[0] = fma2(T1, wA.x, accB[0]);                              \
        accA[1] = fma2(T0, wA.y, accA[1]);                              \
        accB[1] = fma2(T1, wA.y, accB[1]);                              \
        ulonglong2 wB = w4e[1];                                         \
        accA[2] = fma2(T0, wB.x, accA[2]);                              \
        accB[2] = fma2(T1, wB.x, accB[2]);                              \
        accA[3] = fma2(T0, wB.y, accA[3]);                              \
        accB[3] = fma2(T1, wB.y, accB[3]);                              \
        ulonglong2 wC = w4e[2];                                         \
        accA[4] = fma2(T0, wC.x, accA[4]);                              \
        accB[4] = fma2(T1, wC.x, accB[4]);                              \
        accA[5] = fma2(T0, wC.y, accA[5]);                              \
        accB[5] = fma2(T1, wC.y, accB[5]);                              \
        ulonglong2 wD = w4e[3];                                         \
        accA[6] = fma2(T0, wD.x, accA[6]);                              \
        accB[6] = fma2(T1, wD.x, accB[6]);                              \
        accA[7] = fma2(T0, wD.y, accA[7]);                              \
        accB[7] = fma2(T1, wD.y, accB[7]);                              \
        const ulonglong2* w4o = (const ulonglong2*)((wbB) + 64);        \
        ulonglong2 wE = w4o[0];                                         \
        accA[0] = fma2(T2, wE.x, accA[0]);                              \
        accB[0] = fma2(T3, wE.x, accB[0]);                              \
        accA[1] = fma2(T2, wE.y, accA[1]);                              \
        accB[1] = fma2(T3, wE.y, accB[1]);                              \
        ulonglong2 wF = w4o[1];                                         \
        accA[2] = fma2(T2, wF.x, accA[2]);                              \
        accB[2] = fma2(T3, wF.x, accB[2]);                              \
        accA[3] = fma2(T2, wF.y, accA[3]);                              \
        accB[3] = fma2(T3, wF.y, accB[3]);                              \
        ulonglong2 wG = w4o[2];                                         \
        accA[4] = fma2(T2, wG.x, accA[4]);                              \
        accB[4] = fma2(T3, wG.x, accB[4]);                              \
        accA[5] = fma2(T2, wG.y, accA[5]);                              \
        accB[5] = fma2(T3, wG.y, accB[5]);                              \
        ulonglong2 wH = w4o[3];                                         \
        accA[6] = fma2(T2, wH.x, accA[6]);                              \
        accB[6] = fma2(T3, wH.x, accB[6]);                              \
        accA[7] = fma2(T2, wH.y, accA[7]);                              \
        accB[7] = fma2(T3, wH.y, accB[7]);                              \
    } while (0)

// tanh for one stage from packed proj L (ulonglong2) and ep record ptr.
#define STAGE_TANH(L, epB, D0, D1, D2, D3)                              \
    do {                                                                \
        ulonglong2 e0 = *(const ulonglong2*)(epB);                      \
        D0 = tanh2(add2((L).x, e0.x));                                  \
        D1 = tanh2(add2((L).x, e0.y));                                  \
        ulonglong2 e1 = *(const ulonglong2*)((epB) + 16);               \
        D2 = tanh2(add2((L).y, e1.x));                                  \
        D3 = tanh2(add2((L).y, e1.y));                                  \
    } while (0)

__global__ __launch_bounds__(256, 3) void kB(
    const int* __restrict__ omc, const int* __restrict__ ptw,
    const float* __restrict__ eg, const float* __restrict__ ept,
    const float* __restrict__ Wb, const float* __restrict__ bb,
    float* __restrict__ out)
{
    float* sc   = smemB;
    float* attn = smemB + 12800;
    ulonglong2* epsQ = (ulonglong2*)(smemB + 14400);  // [group*128 + a]
    u64*   wbP  = (u64*)(smemB + 15424);              // 128*8
    float* sinv = smemB + 17472;
    float* bbs  = smemB + 17504;
    int*   idxs = (int*)(smemB + 17512);

    const int bx   = blockIdx.x;
    const int b    = bx / 50;
    const int pt   = bx - b * 50;
    const int t    = threadIdx.x;
    const int w    = t >> 5;
    const int lane = t & 31;

    // ---- init loads -------------------------------------------------------
    {
        float* ef = (float*)epsQ;
        for (int i = t; i < 1024; i += 256) {
            int g  = i >> 9;            // group 0..1
            int a  = (i >> 2) & 127;
            int c4 = i & 3;             // 0,1 -> dupA; 2,3 -> dupB
            int pl = g * 2 + (c4 >> 1);
            ef[(g * 128 + a) * 4 + c4] = ept[(long)ptw[pt * PT + pl] * A_D + a];
        }
    }
    for (int i = t; i < A_D * H_; i += 256) {
        float v = Wb[i];
        wbP[i] = pack2(v, v);
    }
    if (t < 8) bbs[t] = bb[t];
    __syncthreads();

    // ---- Phase 1: scores, pipelined stages --------------------------------
    {
        const int pairI = w & 1;             // pathways 2*pairI, 2*pairI+1
        float* scA = sc + (2 * pairI + 0) * H_ * N_;
        float* scB = sc + (2 * pairI + 1) * H_ * N_;
        const char* epBase = (const char*)(epsQ + pairI * 128);

        for (int c = w >> 1; c < NCH; c += 4) {
            u64 accA[H_], accB[H_];
#pragma unroll
            for (int h = 0; h < H_; h++) { accA[h] = 0ull; accB[h] = 0ull; }

            const char* ppB = (const char*)(g_projP + ((b * NCH + c) * 64) * 32 + lane);
            const char* epB = epBase;          // ep for stage s+1 inside loop
            const char* wbB = (const char*)wbP;

            // prologue: T(0) from P(0); L1 = P(1); L2 = P(2)
            u64 T0, T1, T2, T3, U0, U1, U2, U3;
            {
                ulonglong2 L0 = *(const ulonglong2*)ppB;
                STAGE_TANH(L0, epB, T0, T1, T2, T3);
            }
            ulonglong2 L1 = *(const ulonglong2*)(ppB + 512);
            ulonglong2 L2 = *(const ulonglong2*)(ppB + 1024);
            ppB += 1536;
            epB += 32;

            // steady: stages 0..61
#pragma unroll 2
            for (int s = 0; s < 62; s++) {
                STAGE_TANH(L1, epB, U0, U1, U2, U3);     // tanh for s+1
                STAGE_FMA(wbB, T0, T1, T2, T3);          // FMA  for s
                L1 = L2;
                L2 = *(const ulonglong2*)ppB;            // load s+3
                T0 = U0; T1 = U1; T2 = U2; T3 = U3;
                ppB += 512;
                epB += 32;
                wbB += 128;
            }
            // epilogue: stage 62 (tanh 63 from L1), then stage 63
            STAGE_TANH(L1, epB, U0, U1, U2, U3);
            STAGE_FMA(wbB, T0, T1, T2, T3);
            wbB += 128;
            STAGE_FMA(wbB, U0, U1, U2, U3);

            int geneA, geneB;
            bool valid;
            if (c < 6) { geneA = c * 64 + lane; geneB = geneA + 32; valid = true; }
            else       { geneA = 384 + (lane & 7); geneB = geneA + 8; valid = (lane < 8); }
            if (valid) {
#pragma unroll
                for (int h = 0; h < H_; h++) {
                    float xA, yA, xB, yB;
                    unpack2(accA[h], xA, yA);
                    unpack2(accB[h], xB, yB);
                    const float bh = bbs[h];
                    scA[h * N_ + geneA] = xA + bh;
                    scA[h * N_ + geneB] = yA + bh;
                    scB[h * N_ + geneA] = xB + bh;
                    scB[h * N_ + geneB] = yB + bh;
                }
            }
        }
    }
    __syncthreads();

    // ---- Phase 2: softmax over n per head; attn = sum_h -------------------
    const int p    = w >> 1;
    const int half = w & 1;
    const int pg   = pt * PT + p;
    float* scp = sc + p * H_ * N_;
#pragma unroll
    for (int q = 0; q < 4; q++) {
        const int h = half * 4 + q;
        float* row = scp + h * N_;
        float m = -1e30f;
        for (int i = lane; i < N_; i += 32) m = fmaxf(m, row[i]);
#pragma unroll
        for (int o = 16; o; o >>= 1) m = fmaxf(m, __shfl_xor_sync(0xffffffffu, m, o));
        float s = 0.f;
        for (int i = lane; i < N_; i += 32) {
            float e = __expf(row[i] - m);
            row[i] = e;
            s += e;
        }
#pragma unroll
        for (int o = 16; o; o >>= 1) s += __shfl_xor_sync(0xffffffffu, s, o);
        if (lane == 0) sinv[p * H_ + h] = __fdividef(1.f, s);
    }
    __syncthreads();

    {
        float iv[H_];
#pragma unroll
        for (int h = 0; h < H_; h++) iv[h] = sinv[p * H_ + h];
        for (int i = lane; i < 200; i += 32) {
            const int n = half * 200 + i;
            float a = 0.f;
#pragma unroll
            for (int h = 0; h < H_; h++) a = fmaf(scp[h * N_ + n], iv[h], a);
            attn[p * N_ + n] = a;
        }
    }

    // ---- Phase 3: out[b,pg,:] = sum_n attn[n] * E[b,n,:] ------------------
    const ulonglong2* eg4 = (const ulonglong2*)eg;   // 50 per vocab row
    ulonglong2* Es4 = (ulonglong2*)sc;               // 64 genes x 50 recs
    const float* ap = attn + p * N_;
    const int j0 = half * 50;                        // E-slice in u64 units
    u64 acc0 = 0ull, acc1 = 0ull;

    for (int c = 0; c < 7; c++) {
        const int n0 = c * 64;
        const int cnt = min(64, N_ - n0);
        __syncthreads();                    // protect Es/idxs reuse
        if (t < cnt) idxs[t] = omc[b * N_ + n0 + t];
        __syncthreads();
        for (int i = t; i < cnt * 50; i += 256) {
            int n = i / 50, e4 = i - n * 50;
            Es4[n * 50 + e4] = eg4[(long)idxs[n] * 50 + e4];
        }
        __syncthreads();

        const u64* Es = (const u64*)Es4;
#pragma unroll 2
        for (int n = 0; n < cnt; n++) {
            float a = ap[n0 + n];
            u64 av = pack2(a, a);
            const u64* er = Es + n * 100;
            acc0 = fma2(er[j0 + lane], av, acc0);
            if (lane < 18) acc1 = fma2(er[j0 + 32 + lane], av, acc1);
        }
    }

    u64* op = (u64*)out + (long)(b * P_ + pg) * 100;
    op[j0 + lane] = acc0;
    if (lane < 18) op[j0 + 32 + lane] = acc1;
}

// ---------------------------------------------------------------------------
extern "C" void kernel_launch(void* const* d_in, const int* in_sizes, int n_in,
                              void* d_out, int out_size)
{
    const int*   omc = (const int*)  d_in[0];
    const int*   ptw = (const int*)  d_in[1];
    const float* eg  = (const float*)d_in[2];
    const float* ept = (const float*)d_in[3];
    const float* W0  = (const float*)d_in[4];
    const float* b0  = (const float*)d_in[5];
    const float* Wb  = (const float*)d_in[6];
    const float* bb  = (const float*)d_in[7];
    float* out = (float*)d_out;

    kA<<<(B_ * N_) / 8, 128>>>(omc, eg, W0, b0);

    cudaFuncSetAttribute(kB, cudaFuncAttributeMaxDynamicSharedMemorySize,
                         SMEM_B_BYTES);
    kB<<<B_ * (P_ / PT), 256, SMEM_B_BYTES>>>(omc, ptw, eg, ept, Wb, bb, out);
}

// round 11
// speedup vs baseline: 7.3248x; 1.1255x over previous
#include <cuda_runtime.h>

#define B_    16
#define N_    400
#define P_    200
#define E_D   200
#define A_D   128
#define H_    8
#define PT    4      // pathways per block in kernel B
#define NCH   7      // gene chunks of 64 (6 full + 1 partial of 16)

typedef unsigned long long u64;

// proj scratch: ulonglong2 at ((b*NCH + c)*64 + k)*32 + lane =
//   { u64(prj[gLo][2k],  prj[gHi][2k]),  u64(prj[gLo][2k+1], prj[gHi][2k+1]) }
// gLo = c*64+lane, gHi = gLo+32 (c<6); chunk 6: lane<8, gLo=384+lane, gHi=gLo+8.
__device__ ulonglong2 g_projP[B_ * NCH * 64 * 32];

// Wb duplicated pairs: staging (device) -> constant (LDC port, off L1).
__device__ u64 g_wbDup[A_D * H_];             // [a*8 + h] = (w, w)
__constant__ ulonglong2 c_wb4[A_D * H_ / 2];  // [a*4 + h2]: .x=head 2h2, .y=head 2h2+1

__device__ __forceinline__ u64 pack2(float x, float y) {
    u64 r; asm("mov.b64 %0, {%1, %2};" : "=l"(r) : "f"(x), "f"(y)); return r;
}
__device__ __forceinline__ void unpack2(u64 v, float& x, float& y) {
    asm("mov.b64 {%0, %1}, %2;" : "=f"(x), "=f"(y) : "l"(v));
}
__device__ __forceinline__ u64 fma2(u64 a, u64 b, u64 c) {
    u64 d; asm("fma.rn.f32x2 %0, %1, %2, %3;" : "=l"(d) : "l"(a), "l"(b), "l"(c)); return d;
}
__device__ __forceinline__ u64 add2(u64 a, u64 b) {
    u64 d; asm("add.rn.f32x2 %0, %1, %2;" : "=l"(d) : "l"(a), "l"(b)); return d;
}
__device__ __forceinline__ float tanh_ap(float x) {
    float y; asm("tanh.approx.f32 %0, %1;" : "=f"(y) : "f"(x)); return y;
}
__device__ __forceinline__ u64 tanh2(u64 v) {
    float x, y; unpack2(v, x, y);
    return pack2(tanh_ap(x), tanh_ap(y));
}

// ---------------------------------------------------------------------------
// Kernel W: duplicate Wb scalars into (w,w) pairs for f32x2 FMAs.
// ---------------------------------------------------------------------------
__global__ void kW(const float* __restrict__ Wb)
{
    int i = blockIdx.x * 256 + threadIdx.x;
    if (i < A_D * H_) {
        float v = Wb[i];
        g_wbDup[i] = pack2(v, v);
    }
}

// ---------------------------------------------------------------------------
// Kernel A: proj = emb_gene[omc] @ W0 + b0, scattered into gene-paired layout.
// ---------------------------------------------------------------------------
__global__ __launch_bounds__(128) void kA(
    const int* __restrict__ omc, const float* __restrict__ eg,
    const float* __restrict__ W0, const float* __restrict__ b0)
{
    __shared__ float EsT[E_D * 8];   // [e][r]
    __shared__ int idxs[8];
    const int R0 = blockIdx.x * 8;
    const int b  = R0 / N_;
    const int nb = R0 - b * N_;
    const int t  = threadIdx.x;

    if (t < 8) idxs[t] = omc[R0 + t];
    __syncthreads();
    for (int i = t; i < 8 * E_D; i += 128) {
        int r = i / E_D, e = i - r * E_D;
        EsT[e * 8 + r] = eg[(long)idxs[r] * E_D + e];
    }
    __syncthreads();

    const int k  = t & 63;           // a-pair: a = 2k, 2k+1
    const int rg = t >> 6;           // row group (4 rows each)
    const u64* W2 = (const u64*)W0;  // [e][64] pairs
    const u64  bias = ((const u64*)b0)[k];

    u64 acc[4];
#pragma unroll
    for (int r = 0; r < 4; r++) acc[r] = bias;

#pragma unroll 4
    for (int e = 0; e < E_D; e++) {
        u64 w = W2[e * 64 + k];
        const float* er = EsT + e * 8 + rg * 4;
        acc[0] = fma2(pack2(er[0], er[0]), w, acc[0]);
        acc[1] = fma2(pack2(er[1], er[1]), w, acc[1]);
        acc[2] = fma2(pack2(er[2], er[2]), w, acc[2]);
        acc[3] = fma2(pack2(er[3], er[3]), w, acc[3]);
    }

    float* pf = (float*)g_projP;
#pragma unroll
    for (int r = 0; r < 4; r++) {
        const int n = nb + rg * 4 + r;          // gene index within batch b
        const int chunk = n >> 6;
        const int idx   = n & 63;
        int lane, comp;
        if (chunk < 6) { lane = idx & 31; comp = idx >> 5; }
        else           { lane = idx & 7;  comp = idx >> 3; }
        // float layout of ulonglong2 cell: {aLo.gLo, aLo.gHi, aHi.gLo, aHi.gHi}
        const int fbase = (((b * NCH + chunk) * 64 + k) * 32 + lane) * 4 + comp;
        float x, y;
        unpack2(acc[r], x, y);
        pf[fbase]     = x;      // a = 2k
        pf[fbase + 2] = y;      // a = 2k+1
    }
}

// ---------------------------------------------------------------------------
// Kernel B (fused). Block = (b, tile of 4 pathways), 256 threads = 8 warps.
// Phase 1: warp -> pathway PAIR (w&1), chunk slots (w>>1): c, c+4.
//          Pipelined stages (1 stage = 1 LDG.128 = 2 a-values); tanh one
//          stage ahead; proj LDG two ahead. Wb read from CONSTANT memory
//          (LDC port) -> L1 carries only proj LDG + eps LDS.
// Phase 2/3: warp w -> pathway w>>1, half w&1.
//
// SMEM floats:
//   sc    [0, 12800)       scores PT*H*N     (reused as E-chunk 64x200 in ph3)
//   attn  [12800, 14400)   PT*N
//   epsQ  [14400, 15424)   2 groups x 128 a x {dupA u64, dupB u64} (16B recs)
//   sinv  [17472, 17504)
//   bbs   [17504, 17512)
//   idxs  [17512, 17576)   64 ints
// = 70304 bytes -> 3 blocks/SM (~85-reg ceiling)
// ---------------------------------------------------------------------------
#define SMEM_B_FLOATS 17576
#define SMEM_B_BYTES  (SMEM_B_FLOATS * 4)

extern __shared__ float smemB[];

// FMA block for stage with constant base index wc (uniform): even a at wc+0..3,
// odd a at wc+4..7. T0/T1 = pathA/pathB (a even), T2/T3 = (a odd).
#define STAGE_FMA(wc, T0, T1, T2, T3)                                   \
    do {                                                                \
        ulonglong2 wA = c_wb4[(wc) + 0];                                \
        accA[0] = fma2(T0, wA.x, accA[0]);                              \
        accB[0] = fma2(T1, wA.x, accB[0]);                              \
        accA[1] = fma2(T0, wA.y, accA[1]);                              \
        accB[1] = fma2(T1, wA.y, accB[1]);                              \
        ulonglong2 wB = c_wb4[(wc) + 1];                                \
        accA[2] = fma2(T0, wB.x, accA[2]);                              \
        accB[2] = fma2(T1, wB.x, accB[2]);                              \
        accA[3] = fma2(T0, wB.y, accA[3]);                              \
        accB[3] = fma2(T1, wB.y, accB[3]);                              \
        ulonglong2 wC = c_wb4[(wc) + 2];                                \
        accA[4] = fma2(T0, wC.x, accA[4]);                              \
        accB[4] = fma2(T1, wC.x, accB[4]);                              \
        accA[5] = fma2(T0, wC.y, accA[5]);                              \
        accB[5] = fma2(T1, wC.y, accB[5]);                              \
        ulonglong2 wD = c_wb4[(wc) + 3];                                \
        accA[6] = fma2(T0, wD.x, accA[6]);                              \
        accB[6] = fma2(T1, wD.x, accB[6]);                              \
        accA[7] = fma2(T0, wD.y, accA[7]);                              \
        accB[7] = fma2(T1, wD.y, accB[7]);                              \
        ulonglong2 wE = c_wb4[(wc) + 4];                                \
        accA[0] = fma2(T2, wE.x, accA[0]);                              \
        accB[0] = fma2(T3, wE.x, accB[0]);                              \
        accA[1] = fma2(T2, wE.y, accA[1]);                              \
        accB[1] = fma2(T3, wE.y, accB[1]);                              \
        ulonglong2 wF = c_wb4[(wc) + 5];                                \
        accA[2] = fma2(T2, wF.x, accA[2]);                              \
        accB[2] = fma2(T3, wF.x, accB[2]);                              \
        accA[3] = fma2(T2, wF.y, accA[3]);                              \
        accB[3] = fma2(T3, wF.y, accB[3]);                              \
        ulonglong2 wG = c_wb4[(wc) + 6];                                \
        accA[4] = fma2(T2, wG.x, accA[4]);                              \
        accB[4] = fma2(T3, wG.x, accB[4]);                              \
        accA[5] = fma2(T2, wG.y, accA[5]);                              \
        accB[5] = fma2(T3, wG.y, accB[5]);                              \
        ulonglong2 wH = c_wb4[(wc) + 7];                                \
        accA[6] = fma2(T2, wH.x, accA[6]);                              \
        accB[6] = fma2(T3, wH.x, accB[6]);                              \
        accA[7] = fma2(T2, wH.y, accA[7]);                              \
        accB[7] = fma2(T3, wH.y, accB[7]);                              \
    } while (0)

// tanh for one stage from packed proj L (ulonglong2) and ep record ptr.
#define STAGE_TANH(L, epB, D0, D1, D2, D3)                              \
    do {                                                                \
        ulonglong2 e0 = *(const ulonglong2*)(epB);                      \
        D0 = tanh2(add2((L).x, e0.x));                                  \
        D1 = tanh2(add2((L).x, e0.y));                                  \
        ulonglong2 e1 = *(const ulonglong2*)((epB) + 16);               \
        D2 = tanh2(add2((L).y, e1.x));                                  \
        D3 = tanh2(add2((L).y, e1.y));                                  \
    } while (0)

__global__ __launch_bounds__(256, 3) void kB(
    const int* __restrict__ omc, const int* __restrict__ ptw,
    const float* __restrict__ eg, const float* __restrict__ ept,
    const float* __restrict__ bb,
    float* __restrict__ out)
{
    float* sc   = smemB;
    float* attn = smemB + 12800;
    ulonglong2* epsQ = (ulonglong2*)(smemB + 14400);  // [group*128 + a]
    float* sinv = smemB + 17472;
    float* bbs  = smemB + 17504;
    int*   idxs = (int*)(smemB + 17512);

    const int bx   = blockIdx.x;
    const int b    = bx / 50;
    const int pt   = bx - b * 50;
    const int t    = threadIdx.x;
    const int w    = t >> 5;
    const int lane = t & 31;

    // ---- init loads -------------------------------------------------------
    {
        float* ef = (float*)epsQ;
        for (int i = t; i < 1024; i += 256) {
            int g  = i >> 9;            // group 0..1
            int a  = (i >> 2) & 127;
            int c4 = i & 3;             // 0,1 -> dupA; 2,3 -> dupB
            int pl = g * 2 + (c4 >> 1);
            ef[(g * 128 + a) * 4 + c4] = ept[(long)ptw[pt * PT + pl] * A_D + a];
        }
    }
    if (t < 8) bbs[t] = bb[t];
    __syncthreads();

    // ---- Phase 1: scores, pipelined stages, Wb from constant --------------
    {
        const int pairI = w & 1;             // pathways 2*pairI, 2*pairI+1
        float* scA = sc + (2 * pairI + 0) * H_ * N_;
        float* scB = sc + (2 * pairI + 1) * H_ * N_;
        const char* epBase = (const char*)(epsQ + pairI * 128);

        for (int c = w >> 1; c < NCH; c += 4) {
            u64 accA[H_], accB[H_];
#pragma unroll
            for (int h = 0; h < H_; h++) { accA[h] = 0ull; accB[h] = 0ull; }

            const char* ppB = (const char*)(g_projP + ((b * NCH + c) * 64) * 32 + lane);
            const char* epB = epBase;          // ep for stage s+1 inside loop

            // prologue: T(0) from P(0); L1 = P(1); L2 = P(2)
            u64 T0, T1, T2, T3, U0, U1, U2, U3;
            {
                ulonglong2 L0 = *(const ulonglong2*)ppB;
                STAGE_TANH(L0, epB, T0, T1, T2, T3);
            }
            ulonglong2 L1 = *(const ulonglong2*)(ppB + 512);
            ulonglong2 L2 = *(const ulonglong2*)(ppB + 1024);
            ppB += 1536;
            epB += 32;

            int wc = 0;
            // steady: stages 0..61
#pragma unroll 2
            for (int s = 0; s < 62; s++) {
                STAGE_TANH(L1, epB, U0, U1, U2, U3);     // tanh for s+1
                STAGE_FMA(wc, T0, T1, T2, T3);           // FMA  for s
                L1 = L2;
                L2 = *(const ulonglong2*)ppB;            // load s+3
                T0 = U0; T1 = U1; T2 = U2; T3 = U3;
                ppB += 512;
                epB += 32;
                wc += 8;
            }
            // epilogue: stage 62 (tanh 63 from L1), then stage 63
            STAGE_TANH(L1, epB, U0, U1, U2, U3);
            STAGE_FMA(wc, T0, T1, T2, T3);
            STAGE_FMA(wc + 8, U0, U1, U2, U3);

            int geneA, geneB;
            bool valid;
            if (c < 6) { geneA = c * 64 + lane; geneB = geneA + 32; valid = true; }
            else       { geneA = 384 + (lane & 7); geneB = geneA + 8; valid = (lane < 8); }
            if (valid) {
#pragma unroll
                for (int h = 0; h < H_; h++) {
                    float xA, yA, xB, yB;
                    unpack2(accA[h], xA, yA);
                    unpack2(accB[h], xB, yB);
                    const float bh = bbs[h];
                    scA[h * N_ + geneA] = xA + bh;
                    scA[h * N_ + geneB] = yA + bh;
                    scB[h * N_ + geneA] = xB + bh;
                    scB[h * N_ + geneB] = yB + bh;
                }
            }
        }
    }
    __syncthreads();

    // ---- Phase 2: softmax over n per head; attn = sum_h -------------------
    const int p    = w >> 1;
    const int half = w & 1;
    const int pg   = pt * PT + p;
    float* scp = sc + p * H_ * N_;
#pragma unroll
    for (int q = 0; q < 4; q++) {
        const int h = half * 4 + q;
        float* row = scp + h * N_;
        float m = -1e30f;
        for (int i = lane; i < N_; i += 32) m = fmaxf(m, row[i]);
#pragma unroll
        for (int o = 16; o; o >>= 1) m = fmaxf(m, __shfl_xor_sync(0xffffffffu, m, o));
        float s = 0.f;
        for (int i = lane; i < N_; i += 32) {
            float e = __expf(row[i] - m);
            row[i] = e;
            s += e;
        }
#pragma unroll
        for (int o = 16; o; o >>= 1) s += __shfl_xor_sync(0xffffffffu, s, o);
        if (lane == 0) sinv[p * H_ + h] = __fdividef(1.f, s);
    }
    __syncthreads();

    {
        float iv[H_];
#pragma unroll
        for (int h = 0; h < H_; h++) iv[h] = sinv[p * H_ + h];
        for (int i = lane; i < 200; i += 32) {
            const int n = half * 200 + i;
            float a = 0.f;
#pragma unroll
            for (int h = 0; h < H_; h++) a = fmaf(scp[h * N_ + n], iv[h], a);
            attn[p * N_ + n] = a;
        }
    }

    // ---- Phase 3: out[b,pg,:] = sum_n attn[n] * E[b,n,:] ------------------
    const ulonglong2* eg4 = (const ulonglong2*)eg;   // 50 per vocab row
    ulonglong2* Es4 = (ulonglong2*)sc;               // 64 genes x 50 recs
    const float* ap = attn + p * N_;
    const int j0 = half * 50;                        // E-slice in u64 units
    u64 acc0 = 0ull, acc1 = 0ull;

    for (int c = 0; c < 7; c++) {
        const int n0 = c * 64;
        const int cnt = min(64, N_ - n0);
        __syncthreads();                    // protect Es/idxs reuse
        if (t < cnt) idxs[t] = omc[b * N_ + n0 + t];
        __syncthreads();
        for (int i = t; i < cnt * 50; i += 256) {
            int n = i / 50, e4 = i - n * 50;
            Es4[n * 50 + e4] = eg4[(long)idxs[n] * 50 + e4];
        }
        __syncthreads();

        const u64* Es = (const u64*)Es4;
#pragma unroll 2
        for (int n = 0; n < cnt; n++) {
            float a = ap[n0 + n];
            u64 av = pack2(a, a);
            const u64* er = Es + n * 100;
            acc0 = fma2(er[j0 + lane], av, acc0);
            if (lane < 18) acc1 = fma2(er[j0 + 32 + lane], av, acc1);
        }
    }

    u64* op = (u64*)out + (long)(b * P_ + pg) * 100;
    op[j0 + lane] = acc0;
    if (lane < 18) op[j0 + 32 + lane] = acc1;
}

// ---------------------------------------------------------------------------
extern "C" void kernel_launch(void* const* d_in, const int* in_sizes, int n_in,
                              void* d_out, int out_size)
{
    const int*   omc = (const int*)  d_in[0];
    const int*   ptw = (const int*)  d_in[1];
    const float* eg  = (const float*)d_in[2];
    const float* ept = (const float*)d_in[3];
    const float* W0  = (const float*)d_in[4];
    const float* b0  = (const float*)d_in[5];
    const float* Wb  = (const float*)d_in[6];
    const float* bb  = (const float*)d_in[7];
    float* out = (float*)d_out;

    // Wb -> duplicated pairs (device staging) -> constant bank.
    // NOTE: must resolve the SOURCE symbol to a real device pointer;
    // cudaMemcpyToSymbolAsync only resolves the destination symbol (R10 bug).
    kW<<<4, 256>>>(Wb);
    void* srcp = nullptr;
    cudaGetSymbolAddress(&srcp, g_wbDup);
    void* dstp = nullptr;
    cudaGetSymbolAddress(&dstp, c_wb4);
    cudaMemcpyAsync(dstp, srcp, sizeof(u64) * A_D * H_,
                    cudaMemcpyDeviceToDevice, 0);

    kA<<<(B_ * N_) / 8, 128>>>(omc, eg, W0, b0);

    cudaFuncSetAttribute(kB, cudaFuncAttributeMaxDynamicSharedMemorySize,
                         SMEM_B_BYTES);
    kB<<<B_ * (P_ / PT), 256, SMEM_B_BYTES>>>(omc, ptw, eg, ept, bb, out);
}